// round 7
// baseline (speedup 1.0000x reference)
#include <cuda_runtime.h>
#include <cuda_bf16.h>
#include <math.h>

// ---------------- problem constants ----------------
#define NB   16          // batch
#define LSEQ 256         // sequence length (TY+1)
#define ENC  512
#define EMB  256
#define DEC  512
#define NV   32000
#define G4   2048        // 4*DEC
#define MROWS 4096       // NB*LSEQ

// ---------------- scratch (__device__ globals; no allocs) ----------------
__device__ float g_seq [NB*LSEQ*EMB];        //  4 MB  [b][t][EMB]
__device__ float g_xw  [LSEQ*G4*NB];         // 32 MB  [t][j][b]
__device__ float g_cat [NB*LSEQ*2*DEC];      // 16 MB  [b][t][ mix(512) | h1(512) ]
__device__ float g_attn[MROWS*DEC];          //  8 MB  [m][512]
__device__ float g_h2  [MROWS*DEC];          //  8 MB  [m][512]
__device__ float g_hbuf[2*NB*DEC];           // h double buffer
__device__ unsigned          g_bar_cnt;
__device__ volatile unsigned g_bar_gen;

// bf16 hi/lo split operands for fc2 tensor-core GEMM
__device__ __nv_bfloat16 g_Ah[MROWS*DEC];    //  4 MB
__device__ __nv_bfloat16 g_Al[MROWS*DEC];    //  4 MB
__device__ __nv_bfloat16 g_Bh[NV*DEC];       // 32 MB
__device__ __nv_bfloat16 g_Bl[NV*DEC];       // 32 MB

__device__ __forceinline__ float sigf(float x){ return 1.0f/(1.0f+__expf(-x)); }

// ---------------- grid barrier (self-resetting, capture-safe) ----------------
__device__ __forceinline__ void grid_barrier()
{
    __syncthreads();
    if (threadIdx.x == 0) {
        __threadfence();
        unsigned gen = g_bar_gen;
        if (atomicAdd(&g_bar_cnt, 1u) == gridDim.x - 1u) {
            atomicExch(&g_bar_cnt, 0u);
            __threadfence();
            g_bar_gen = gen + 1u;
        } else {
            while (g_bar_gen == gen) { }
        }
    }
    __syncthreads();
}

// ---------------- kernel 1: fc1 + BatchNorm (batch stats) -> seq[:,0,:] ----------------
__global__ void __launch_bounds__(256) fc1_bn_kernel(
    const float* __restrict__ x,     // [16,512]
    const float* __restrict__ w,     // [256,512]
    const float* __restrict__ bias,  // [256]
    const float* __restrict__ gam,   // [256]
    const float* __restrict__ bet)   // [256]
{
    __shared__ float xs[NB*ENC];     // 32 KB
    int tid = threadIdx.x;
    for (int i = tid; i < NB*ENC/4; i += 256)
        ((float4*)xs)[i] = ((const float4*)x)[i];
    __syncthreads();

    int j = tid;                     // one feature per thread (EMB == 256)
    float f[NB];
    #pragma unroll
    for (int b = 0; b < NB; b++) f[b] = bias[j];

    const float4* w4 = (const float4*)(w + j*ENC);
    for (int k4 = 0; k4 < ENC/4; k4++) {
        float4 ww = w4[k4];
        #pragma unroll
        for (int b = 0; b < NB; b++) {
            float4 xx = ((float4*)xs)[b*(ENC/4) + k4];
            f[b] += ww.x*xx.x + ww.y*xx.y + ww.z*xx.z + ww.w*xx.w;
        }
    }
    float mu = 0.f;
    #pragma unroll
    for (int b = 0; b < NB; b++) mu += f[b];
    mu *= (1.0f/NB);
    float var = 0.f;
    #pragma unroll
    for (int b = 0; b < NB; b++) { float d = f[b]-mu; var += d*d; }
    var *= (1.0f/NB);
    float s = rsqrtf(var + 1e-5f) * gam[j];
    float bb = bet[j];
    #pragma unroll
    for (int b = 0; b < NB; b++)
        g_seq[b*(LSEQ*EMB) + j] = (f[b]-mu)*s + bb;   // t = 0
}

// ---------------- kernel 2: embedding gather -> seq[:,1:,:] ----------------
__global__ void embed_kernel(const int* __restrict__ y,      // [16,255]
                             const float* __restrict__ emb)  // [32000,256]
{
    int blk = blockIdx.x;            // 16*255 blocks
    int b = blk / (LSEQ-1), t = blk % (LSEQ-1);
    int row = y[b*(LSEQ-1) + t];
    const float4* src = (const float4*)(emb + (long)row*EMB);
    float4* dst = (float4*)(g_seq + b*(LSEQ*EMB) + (t+1)*EMB);
    dst[threadIdx.x] = src[threadIdx.x];   // 64 threads * float4 = 256 floats
}

// ---------------- kernel 3: SGEMM  C = A[M,K] * B[N,K]^T (+bias) ----------------
// MODE 0: C[m*N+n]   (row-major), optional tanh
// MODE 1: C[t*(N*16) + n*16 + b] with m = b*LSEQ + t   (LSTM xw layout)
template<int MODE, bool DOTANH>
__global__ void __launch_bounds__(256) sgemm_tn(
    const float* __restrict__ A, const float* __restrict__ B,
    const float* __restrict__ bias0, const float* __restrict__ bias1,
    float* __restrict__ C, int M, int N, int K)
{
    __shared__ float As[8][132];
    __shared__ float Bs[8][132];
    int tid = threadIdx.x;
    int bn = blockIdx.x, bm = blockIdx.y;

    int lrow = tid >> 1;
    int colq = (tid & 1) * 4;
    const float* Ag = A + (long)(bm*128 + lrow)*K + colq;
    const float* Bg = B + (long)(bn*128 + lrow)*K + colq;

    int tx = tid & 15, ty = tid >> 4;
    float acc[8][8];
    #pragma unroll
    for (int i = 0; i < 8; i++)
        #pragma unroll
        for (int j = 0; j < 8; j++) acc[i][j] = 0.f;

    for (int k0 = 0; k0 < K; k0 += 8) {
        float4 av = *(const float4*)(Ag + k0);
        float4 bv = *(const float4*)(Bg + k0);
        __syncthreads();
        As[colq+0][lrow] = av.x; As[colq+1][lrow] = av.y;
        As[colq+2][lrow] = av.z; As[colq+3][lrow] = av.w;
        Bs[colq+0][lrow] = bv.x; Bs[colq+1][lrow] = bv.y;
        Bs[colq+2][lrow] = bv.z; Bs[colq+3][lrow] = bv.w;
        __syncthreads();
        #pragma unroll
        for (int k = 0; k < 8; k++) {
            float a[8], br[8];
            *(float4*)&a[0]  = *(float4*)&As[k][ty*8];
            *(float4*)&a[4]  = *(float4*)&As[k][ty*8+4];
            *(float4*)&br[0] = *(float4*)&Bs[k][tx*8];
            *(float4*)&br[4] = *(float4*)&Bs[k][tx*8+4];
            #pragma unroll
            for (int i = 0; i < 8; i++)
                #pragma unroll
                for (int j = 0; j < 8; j++)
                    acc[i][j] += a[i]*br[j];
        }
    }

    int m0 = bm*128 + ty*8;
    int n0 = bn*128 + tx*8;
    float bs[8];
    #pragma unroll
    for (int j = 0; j < 8; j++) {
        float v = 0.f;
        if (bias0) v += bias0[n0+j];
        if (bias1) v += bias1[n0+j];
        bs[j] = v;
    }
    #pragma unroll
    for (int i = 0; i < 8; i++) {
        int m = m0 + i;
        #pragma unroll
        for (int j = 0; j < 8; j++) {
            float v = acc[i][j] + bs[j];
            if (DOTANH) v = tanhf(v);
            int n = n0 + j;
            if (MODE == 0) {
                C[(long)m*N + n] = v;
            } else {
                int b = m >> 8, t = m & 255;
                C[(long)t*(N*NB) + n*NB + b] = v;
            }
        }
    }
}

// ---------------- kernel 4: persistent LSTM (128 CTAs) ----------------
#define LSTM_CTAS 128
#define WP 130   // smem row stride in float4
#define HP 130

__global__ void __launch_bounds__(256, 1) lstm_kernel(
    const float* __restrict__ xw,
    const float* __restrict__ Whh,   // [2048,512]
    float* __restrict__ out, long bstr, long tstr)
{
    extern __shared__ float4 smem[];
    float4* ws = smem;               // 16*WP
    float4* hs = smem + 16*WP;       // 16*HP
    float*  gx = (float*)(smem + 16*WP + 16*HP);   // 256 floats

    int tid = threadIdx.x, cta = blockIdx.x;
    int gate = tid >> 6, dl = (tid >> 4) & 3, b = tid & 15;
    int jl = gate*4 + dl;
    int j  = gate*512 + cta*4 + dl;

    for (int i = tid; i < 16*128; i += 256) {
        int r = i >> 7, c = i & 127;
        int jj = (r >> 2)*512 + cta*4 + (r & 3);
        ws[r*WP + c] = ((const float4*)Whh)[jj*128 + c];
    }
    for (int i = cta*256 + tid; i < NB*DEC; i += LSTM_CTAS*256)
        g_hbuf[i] = 0.f;

    float c_reg = 0.f;
    grid_barrier();

    for (int t = 0; t < LSEQ; t++) {
        const float* hsrc = g_hbuf + (t & 1)*(NB*DEC);
        for (int i = tid; i < NB*128; i += 256) {
            int bb = i >> 7, c = i & 127;
            hs[bb*HP + c] = __ldcg(((const float4*)hsrc) + bb*128 + c);
        }
        __syncthreads();

        float acc = xw[(long)t*(G4*NB) + j*NB + b];
        const float4* wr = ws + jl*WP;
        const float4* hr = hs + b*HP;
        #pragma unroll 4
        for (int k4 = 0; k4 < 128; k4++) {
            float4 w4 = wr[k4];
            float4 h4 = hr[k4];
            acc += w4.x*h4.x + w4.y*h4.y + w4.z*h4.z + w4.w*h4.w;
        }
        gx[tid] = acc;
        __syncthreads();

        if (tid < 64) {
            float ig = sigf(gx[tid]);
            float fg = sigf(gx[64 + tid]);
            float gg = tanhf(gx[128 + tid]);
            float og = sigf(gx[192 + tid]);
            c_reg = fg*c_reg + ig*gg;
            float h = og * tanhf(c_reg);
            int ddl = tid >> 4, bb = tid & 15;
            int d = cta*4 + ddl;
            __stcg(&g_hbuf[((t+1) & 1)*(NB*DEC) + bb*DEC + d], h);
            out[bb*bstr + (long)t*tstr + d] = h;
        }
        grid_barrier();
    }
}

// ---------------- kernel 5: causal self-attention (CTA per (q,b)) ----------------
__global__ void __launch_bounds__(256) attn_kernel()
{
    __shared__ float hqs[512];
    __shared__ float sc[256];
    __shared__ float red[256];
    int q = blockIdx.x, b = blockIdx.y;
    int tid = threadIdx.x;
    int nk = q + 1;
    float* catb = g_cat + (long)b*(LSEQ*2*DEC);

    if (tid < 128)
        ((float4*)hqs)[tid] = ((const float4*)(catb + q*1024 + 512))[tid];
    __syncthreads();

    int w = tid >> 5, lane = tid & 31;
    for (int k = w; k < nk; k += 8) {
        const float4* hk = (const float4*)(catb + k*1024 + 512);
        float s = 0.f;
        #pragma unroll
        for (int i = 0; i < 4; i++) {
            float4 a = ((float4*)hqs)[lane + 32*i];
            float4 c = hk[lane + 32*i];
            s += a.x*c.x + a.y*c.y + a.z*c.z + a.w*c.w;
        }
        #pragma unroll
        for (int off = 16; off; off >>= 1) s += __shfl_xor_sync(0xffffffffu, s, off);
        if (lane == 0) sc[k] = s;
    }
    __syncthreads();

    float v = (tid < nk) ? sc[tid] : -INFINITY;
    red[tid] = v; __syncthreads();
    #pragma unroll
    for (int s = 128; s; s >>= 1) {
        if (tid < s) red[tid] = fmaxf(red[tid], red[tid+s]);
        __syncthreads();
    }
    float mx = red[0]; __syncthreads();
    float e = (tid < nk) ? __expf(v - mx) : 0.f;
    red[tid] = e; __syncthreads();
    #pragma unroll
    for (int s = 128; s; s >>= 1) {
        if (tid < s) red[tid] += red[tid+s];
        __syncthreads();
    }
    float inv = 1.f / red[0];
    __syncthreads();
    if (tid < nk) sc[tid] = e * inv;
    __syncthreads();

    float a0 = 0.f, a1 = 0.f;
    for (int k = 0; k < nk; k++) {
        float wk = sc[k];
        const float* hk = catb + k*1024 + 512;
        a0 += wk * hk[tid];
        a1 += wk * hk[tid + 256];
    }
    catb[q*1024 + tid]       = a0;
    catb[q*1024 + tid + 256] = a1;
}

// ---------------- kernel 6: fp32 -> bf16 hi/lo split ----------------
__global__ void __launch_bounds__(256) split_bf16_kernel(
    const float* __restrict__ src, __nv_bfloat16* __restrict__ hi,
    __nv_bfloat16* __restrict__ lo, int n)
{
    for (int i = blockIdx.x*256 + threadIdx.x; i < n; i += gridDim.x*256) {
        float v = src[i];
        __nv_bfloat16 h = __float2bfloat16(v);
        hi[i] = h;
        lo[i] = __float2bfloat16(v - __bfloat162float(h));
    }
}

// ---------------- kernel 7: fc2 tensor-core GEMM (bf16 hi/lo, fp32 acc) ----------------
// C[4096,32000] = (Ah+Al)[4096,512] * (Bh+Bl)[32000,512]^T + bias
// CTA tile 128x128, k-step 32, cp.async double buffer, 8 warps (warp tile 32x64)
// Fragments loaded with ldmatrix.x4 (conflict-free with 80B row stride).
#define FC2_KS   32
#define AST      40                       // smem row stride in bf16 (80B, conflict-free)
#define MATSZ    (128*AST)                // bf16 elems per matrix tile
#define FC2_SMEM (2*4*MATSZ*2)            // 81920 B

__device__ __forceinline__ void mma_bf16(float* c, const unsigned* a, const unsigned* b)
{
    asm volatile(
        "mma.sync.aligned.m16n8k16.row.col.f32.bf16.bf16.f32 "
        "{%0,%1,%2,%3}, {%4,%5,%6,%7}, {%8,%9}, {%0,%1,%2,%3};\n"
        : "+f"(c[0]), "+f"(c[1]), "+f"(c[2]), "+f"(c[3])
        : "r"(a[0]), "r"(a[1]), "r"(a[2]), "r"(a[3]), "r"(b[0]), "r"(b[1]));
}

__device__ __forceinline__ void ldsm_x4(unsigned& r0, unsigned& r1, unsigned& r2,
                                        unsigned& r3, unsigned addr)
{
    asm volatile("ldmatrix.sync.aligned.m8n8.x4.shared.b16 {%0,%1,%2,%3}, [%4];\n"
                 : "=r"(r0), "=r"(r1), "=r"(r2), "=r"(r3) : "r"(addr));
}

__global__ void __launch_bounds__(256, 2) fc2_mma_kernel(
    const __nv_bfloat16* __restrict__ Ah, const __nv_bfloat16* __restrict__ Al,
    const __nv_bfloat16* __restrict__ Bh, const __nv_bfloat16* __restrict__ Bl,
    const float* __restrict__ bias, float* __restrict__ C)
{
    extern __shared__ __nv_bfloat16 sm[];
    const int tid = threadIdx.x;
    const int lane = tid & 31;
    const int warp = tid >> 5;
    const int warp_m = warp >> 1;        // 0..3 -> rows 32*warp_m
    const int warp_n = warp & 1;         // 0..1 -> cols 64*warp_n
    const int m0 = blockIdx.y * 128;
    const int n0 = blockIdx.x * 128;

    unsigned sbase = (unsigned)__cvta_generic_to_shared(sm);

    const __nv_bfloat16* gsrc0 = Ah + (long)m0*DEC;
    const __nv_bfloat16* gsrc1 = Al + (long)m0*DEC;
    const __nv_bfloat16* gsrc2 = Bh + (long)n0*DEC;
    const __nv_bfloat16* gsrc3 = Bl + (long)n0*DEC;

    // issue cp.async (16B each) for one k-chunk into buffer `buf`
    auto issue_load = [&](int buf, int k0) {
        const __nv_bfloat16* gs[4] = {gsrc0, gsrc1, gsrc2, gsrc3};
        #pragma unroll
        for (int mat = 0; mat < 4; mat++) {
            #pragma unroll
            for (int rep = 0; rep < 2; rep++) {
                int idx  = tid + rep*256;            // 0..511
                int row  = idx >> 2;
                int quad = idx & 3;
                unsigned daddr = sbase + ((buf*4 + mat)*MATSZ + row*AST + quad*8)*2;
                const void* g = gs[mat] + (long)row*DEC + k0 + quad*8;
                asm volatile("cp.async.cg.shared.global [%0], [%1], 16;\n"
                             :: "r"(daddr), "l"(g));
            }
        }
        asm volatile("cp.async.commit_group;\n");
    };

    float acc[2][8][4];
    #pragma unroll
    for (int i = 0; i < 2; i++)
        #pragma unroll
        for (int j = 0; j < 8; j++)
            #pragma unroll
            for (int r = 0; r < 4; r++) acc[i][j][r] = 0.f;

    issue_load(0, 0);

    // ldmatrix lane address components (bytes within a tile)
    const int lrow16 = lane & 15;              // row within 16-row group
    const int lcolhi = (lane >> 4) * 16;       // +16B for upper half of lanes

    int buf = 0;
    for (int ks = 0; ks < DEC/FC2_KS; ks++) {
        asm volatile("cp.async.wait_group 0;\n");
        __syncthreads();
        if (ks + 1 < DEC/FC2_KS) issue_load(buf ^ 1, (ks+1)*FC2_KS);

        unsigned bAh = sbase + (buf*4 + 0)*MATSZ*2;
        unsigned bAl = sbase + (buf*4 + 1)*MATSZ*2;
        unsigned bBh = sbase + (buf*4 + 2)*MATSZ*2;
        unsigned bBl = sbase + (buf*4 + 3)*MATSZ*2;

        #pragma unroll
        for (int k16 = 0; k16 < 2; k16++) {
            int kb = k16*32 + lcolhi;          // byte offset in k
            // A fragments: 2 m16 tiles, hi and lo
            unsigned a_h[2][4], a_l[2][4];
            #pragma unroll
            for (int im = 0; im < 2; im++) {
                unsigned roff = (warp_m*32 + im*16 + lrow16) * (AST*2) + kb;
                ldsm_x4(a_h[im][0], a_h[im][1], a_h[im][2], a_h[im][3], bAh + roff);
                ldsm_x4(a_l[im][0], a_l[im][1], a_l[im][2], a_l[im][3], bAl + roff);
            }
            // B fragments: 8 n8 tiles as 4 n16 ldmatrix.x4, hi and lo
            unsigned b_h[8][2], b_l[8][2];
            #pragma unroll
            for (int in2 = 0; in2 < 4; in2++) {
                unsigned roff = (warp_n*64 + in2*16 + lrow16) * (AST*2) + kb;
                unsigned r0, r1, r2, r3;
                ldsm_x4(r0, r1, r2, r3, bBh + roff);
                b_h[in2*2+0][0] = r0; b_h[in2*2+0][1] = r2;
                b_h[in2*2+1][0] = r1; b_h[in2*2+1][1] = r3;
                ldsm_x4(r0, r1, r2, r3, bBl + roff);
                b_l[in2*2+0][0] = r0; b_l[in2*2+0][1] = r2;
                b_l[in2*2+1][0] = r1; b_l[in2*2+1][1] = r3;
            }
            #pragma unroll
            for (int im = 0; im < 2; im++)
                #pragma unroll
                for (int in = 0; in < 8; in++) {
                    mma_bf16(acc[im][in], a_h[im], b_h[in]);
                    mma_bf16(acc[im][in], a_h[im], b_l[in]);
                    mma_bf16(acc[im][in], a_l[im], b_h[in]);
                }
        }
        buf ^= 1;
        __syncthreads();
    }

    // epilogue: add bias, store fp32
    #pragma unroll
    for (int im = 0; im < 2; im++) {
        int row = m0 + warp_m*32 + im*16 + (lane >> 2);
        #pragma unroll
        for (int in = 0; in < 8; in++) {
            int col = n0 + warp_n*64 + in*8 + (lane & 3)*2;
            float b0 = bias[col], b1 = bias[col+1];
            float2 v0 = make_float2(acc[im][in][0] + b0, acc[im][in][1] + b1);
            float2 v1 = make_float2(acc[im][in][2] + b0, acc[im][in][3] + b1);
            *(float2*)(C + (long)row*NV + col)     = v0;
            *(float2*)(C + (long)(row+8)*NV + col) = v1;
        }
    }
}

// ---------------- launch ----------------
extern "C" void kernel_launch(void* const* d_in, const int* in_sizes, int n_in,
                              void* d_out, int out_size)
{
    const float* x       = (const float*)d_in[0];
    const int*   y       = (const int*)  d_in[1];
    const float* fc1_w   = (const float*)d_in[2];
    const float* fc1_b   = (const float*)d_in[3];
    const float* bn_g    = (const float*)d_in[4];
    const float* bn_b    = (const float*)d_in[5];
    const float* emb     = (const float*)d_in[6];
    const float* l1_Wih  = (const float*)d_in[7];
    const float* l1_Whh  = (const float*)d_in[8];
    const float* l1_bih  = (const float*)d_in[9];
    const float* l1_bhh  = (const float*)d_in[10];
    const float* attn_W  = (const float*)d_in[11];
    const float* dc_Wih  = (const float*)d_in[12];
    const float* dc_Whh  = (const float*)d_in[13];
    const float* dc_bih  = (const float*)d_in[14];
    const float* dc_bhh  = (const float*)d_in[15];
    const float* fc2_w   = (const float*)d_in[16];
    const float* fc2_b   = (const float*)d_in[17];
    float* out = (float*)d_out;

    float *p_seq, *p_xw, *p_cat, *p_attn, *p_h2;
    __nv_bfloat16 *p_Ah, *p_Al, *p_Bh, *p_Bl;
    cudaGetSymbolAddress((void**)&p_seq,  g_seq);
    cudaGetSymbolAddress((void**)&p_xw,   g_xw);
    cudaGetSymbolAddress((void**)&p_cat,  g_cat);
    cudaGetSymbolAddress((void**)&p_attn, g_attn);
    cudaGetSymbolAddress((void**)&p_h2,   g_h2);
    cudaGetSymbolAddress((void**)&p_Ah,   g_Ah);
    cudaGetSymbolAddress((void**)&p_Al,   g_Al);
    cudaGetSymbolAddress((void**)&p_Bh,   g_Bh);
    cudaGetSymbolAddress((void**)&p_Bl,   g_Bl);

    int lstm_smem = (16*WP + 16*HP)*16 + 256*4;
    cudaFuncSetAttribute(lstm_kernel, cudaFuncAttributeMaxDynamicSharedMemorySize, lstm_smem);
    cudaFuncSetAttribute(fc2_mma_kernel, cudaFuncAttributeMaxDynamicSharedMemorySize, FC2_SMEM);

    // 1. fc1 + BN
    fc1_bn_kernel<<<1, 256>>>(x, fc1_w, fc1_b, bn_g, bn_b);
    // 2. embedding
    embed_kernel<<<NB*(LSEQ-1), 64>>>(y, emb);
    // (split fc2 weights while the front of the pipeline runs)
    split_bf16_kernel<<<2048, 256>>>(fc2_w, p_Bh, p_Bl, NV*DEC);
    // 3. xw1 = seq @ l1_Wih^T + biases   (LSTM layout)
    sgemm_tn<1,false><<<dim3(G4/128, MROWS/128), 256>>>(
        p_seq, l1_Wih, l1_bih, l1_bhh, p_xw, MROWS, G4, EMB);
    // 4. LSTM 1  ->  g_cat[b][t][512:1024]
    lstm_kernel<<<LSTM_CTAS, 256, lstm_smem>>>(
        p_xw, l1_Whh, p_cat + 512, (long)LSEQ*2*DEC, (long)2*DEC);
    // 5. attention -> g_cat[b][t][0:512]
    attn_kernel<<<dim3(LSEQ, NB), 256>>>();
    // 6. attn = tanh(cat @ attn_W^T)
    sgemm_tn<0,true><<<dim3(DEC/128, MROWS/128), 256>>>(
        p_cat, attn_W, nullptr, nullptr, p_attn, MROWS, DEC, 2*DEC);
    // 7. xw2 = attn @ dc_Wih^T + biases  (LSTM layout)
    sgemm_tn<1,false><<<dim3(G4/128, MROWS/128), 256>>>(
        p_attn, dc_Wih, dc_bih, dc_bhh, p_xw, MROWS, G4, DEC);
    // 8. LSTM 2 -> g_h2[m][d]
    lstm_kernel<<<LSTM_CTAS, 256, lstm_smem>>>(
        p_xw, dc_Whh, p_h2, (long)LSEQ*DEC, (long)DEC);
    // 9. split h2 into bf16 hi/lo
    split_bf16_kernel<<<1024, 256>>>(p_h2, p_Ah, p_Al, MROWS*DEC);
    // 10. fc2 tensor-core GEMM -> d_out
    fc2_mma_kernel<<<dim3(NV/128, MROWS/128), 256, FC2_SMEM>>>(
        p_Ah, p_Al, p_Bh, p_Bl, fc2_b, out);
}

// round 8
// speedup vs baseline: 1.0554x; 1.0554x over previous
#include <cuda_runtime.h>
#include <cuda_bf16.h>
#include <math.h>

// ---------------- problem constants ----------------
#define NB   16          // batch
#define LSEQ 256         // sequence length (TY+1)
#define ENC  512
#define EMB  256
#define DEC  512
#define NV   32000
#define G4   2048        // 4*DEC
#define MROWS 4096       // NB*LSEQ

// ---------------- scratch (__device__ globals; no allocs) ----------------
__device__ float g_seq [NB*LSEQ*EMB];        //  4 MB  [b][t][EMB]
__device__ float g_xw  [LSEQ*G4*NB];         // 32 MB  [t][j][b]
__device__ float g_cat [NB*LSEQ*2*DEC];      // 16 MB  [b][t][ mix(512) | h1(512) ]
__device__ float g_attn[MROWS*DEC];          //  8 MB  [m][512]
__device__ float g_h2  [MROWS*DEC];          //  8 MB  [m][512]
__device__ float g_hbuf[2*NB*DEC];           // h double buffer
__device__ unsigned          g_bar_cnt;
__device__ volatile unsigned g_bar_gen;

__device__ __forceinline__ float sigf(float x){ return 1.0f/(1.0f+__expf(-x)); }

// ---------------- grid barrier (self-resetting, capture-safe) ----------------
__device__ __forceinline__ void grid_barrier()
{
    __syncthreads();
    if (threadIdx.x == 0) {
        __threadfence();
        unsigned gen = g_bar_gen;
        if (atomicAdd(&g_bar_cnt, 1u) == gridDim.x - 1u) {
            atomicExch(&g_bar_cnt, 0u);
            __threadfence();
            g_bar_gen = gen + 1u;
        } else {
            while (g_bar_gen == gen) { }
        }
    }
    __syncthreads();
}

// ---------------- kernel 1: fc1 + BatchNorm (batch stats) -> seq[:,0,:] ----------------
__global__ void __launch_bounds__(256) fc1_bn_kernel(
    const float* __restrict__ x,     // [16,512]
    const float* __restrict__ w,     // [256,512]
    const float* __restrict__ bias,  // [256]
    const float* __restrict__ gam,   // [256]
    const float* __restrict__ bet)   // [256]
{
    __shared__ float xs[NB*ENC];     // 32 KB
    int tid = threadIdx.x;
    for (int i = tid; i < NB*ENC/4; i += 256)
        ((float4*)xs)[i] = ((const float4*)x)[i];
    __syncthreads();

    int j = tid;                     // one feature per thread (EMB == 256)
    float f[NB];
    #pragma unroll
    for (int b = 0; b < NB; b++) f[b] = bias[j];

    const float4* w4 = (const float4*)(w + j*ENC);
    for (int k4 = 0; k4 < ENC/4; k4++) {
        float4 ww = w4[k4];
        #pragma unroll
        for (int b = 0; b < NB; b++) {
            float4 xx = ((float4*)xs)[b*(ENC/4) + k4];
            f[b] += ww.x*xx.x + ww.y*xx.y + ww.z*xx.z + ww.w*xx.w;
        }
    }
    float mu = 0.f;
    #pragma unroll
    for (int b = 0; b < NB; b++) mu += f[b];
    mu *= (1.0f/NB);
    float var = 0.f;
    #pragma unroll
    for (int b = 0; b < NB; b++) { float d = f[b]-mu; var += d*d; }
    var *= (1.0f/NB);
    float s = rsqrtf(var + 1e-5f) * gam[j];
    float bb = bet[j];
    #pragma unroll
    for (int b = 0; b < NB; b++)
        g_seq[b*(LSEQ*EMB) + j] = (f[b]-mu)*s + bb;   // t = 0
}

// ---------------- kernel 2: embedding gather -> seq[:,1:,:] ----------------
__global__ void embed_kernel(const int* __restrict__ y,      // [16,255]
                             const float* __restrict__ emb)  // [32000,256]
{
    int blk = blockIdx.x;            // 16*255 blocks
    int b = blk / (LSEQ-1), t = blk % (LSEQ-1);
    int row = y[b*(LSEQ-1) + t];
    const float4* src = (const float4*)(emb + (long)row*EMB);
    float4* dst = (float4*)(g_seq + b*(LSEQ*EMB) + (t+1)*EMB);
    dst[threadIdx.x] = src[threadIdx.x];   // 64 threads * float4 = 256 floats
}

// ---------------- kernel 3: SGEMM  C = A[M,K] * B[N,K]^T (+bias) ----------------
// MODE 0: C[m*N+n]   (row-major), optional tanh
// MODE 1: C[t*(N*16) + n*16 + b] with m = b*LSEQ + t   (LSTM xw layout)
template<int MODE, bool DOTANH>
__global__ void __launch_bounds__(256) sgemm_tn(
    const float* __restrict__ A, const float* __restrict__ B,
    const float* __restrict__ bias0, const float* __restrict__ bias1,
    float* __restrict__ C, int M, int N, int K)
{
    __shared__ float As[8][132];
    __shared__ float Bs[8][132];
    int tid = threadIdx.x;
    int bn = blockIdx.x, bm = blockIdx.y;

    int lrow = tid >> 1;
    int colq = (tid & 1) * 4;
    const float* Ag = A + (long)(bm*128 + lrow)*K + colq;
    const float* Bg = B + (long)(bn*128 + lrow)*K + colq;

    int tx = tid & 15, ty = tid >> 4;
    float acc[8][8];
    #pragma unroll
    for (int i = 0; i < 8; i++)
        #pragma unroll
        for (int j = 0; j < 8; j++) acc[i][j] = 0.f;

    for (int k0 = 0; k0 < K; k0 += 8) {
        float4 av = *(const float4*)(Ag + k0);
        float4 bv = *(const float4*)(Bg + k0);
        __syncthreads();
        As[colq+0][lrow] = av.x; As[colq+1][lrow] = av.y;
        As[colq+2][lrow] = av.z; As[colq+3][lrow] = av.w;
        Bs[colq+0][lrow] = bv.x; Bs[colq+1][lrow] = bv.y;
        Bs[colq+2][lrow] = bv.z; Bs[colq+3][lrow] = bv.w;
        __syncthreads();
        #pragma unroll
        for (int k = 0; k < 8; k++) {
            float a[8], br[8];
            *(float4*)&a[0]  = *(float4*)&As[k][ty*8];
            *(float4*)&a[4]  = *(float4*)&As[k][ty*8+4];
            *(float4*)&br[0] = *(float4*)&Bs[k][tx*8];
            *(float4*)&br[4] = *(float4*)&Bs[k][tx*8+4];
            #pragma unroll
            for (int i = 0; i < 8; i++)
                #pragma unroll
                for (int j = 0; j < 8; j++)
                    acc[i][j] += a[i]*br[j];
        }
    }

    int m0 = bm*128 + ty*8;
    int n0 = bn*128 + tx*8;
    float bs[8];
    #pragma unroll
    for (int j = 0; j < 8; j++) {
        float v = 0.f;
        if (bias0) v += bias0[n0+j];
        if (bias1) v += bias1[n0+j];
        bs[j] = v;
    }
    #pragma unroll
    for (int i = 0; i < 8; i++) {
        int m = m0 + i;
        #pragma unroll
        for (int j = 0; j < 8; j++) {
            float v = acc[i][j] + bs[j];
            if (DOTANH) v = tanhf(v);
            int n = n0 + j;
            if (MODE == 0) {
                C[(long)m*N + n] = v;
            } else {
                int b = m >> 8, t = m & 255;
                C[(long)t*(N*NB) + n*NB + b] = v;
            }
        }
    }
}

// ---------------- kernel 4: persistent LSTM (128 CTAs) ----------------
#define LSTM_CTAS 128
#define WP 130   // smem row stride in float4
#define HP 130

__global__ void __launch_bounds__(256, 1) lstm_kernel(
    const float* __restrict__ xw,
    const float* __restrict__ Whh,   // [2048,512]
    float* __restrict__ out, long bstr, long tstr)
{
    extern __shared__ float4 smem[];
    float4* ws = smem;               // 16*WP
    float4* hs = smem + 16*WP;       // 16*HP
    float*  gx = (float*)(smem + 16*WP + 16*HP);   // 256 floats

    int tid = threadIdx.x, cta = blockIdx.x;
    int gate = tid >> 6, dl = (tid >> 4) & 3, b = tid & 15;
    int jl = gate*4 + dl;
    int j  = gate*512 + cta*4 + dl;

    for (int i = tid; i < 16*128; i += 256) {
        int r = i >> 7, c = i & 127;
        int jj = (r >> 2)*512 + cta*4 + (r & 3);
        ws[r*WP + c] = ((const float4*)Whh)[jj*128 + c];
    }
    for (int i = cta*256 + tid; i < NB*DEC; i += LSTM_CTAS*256)
        g_hbuf[i] = 0.f;

    float c_reg = 0.f;
    grid_barrier();

    for (int t = 0; t < LSEQ; t++) {
        const float* hsrc = g_hbuf + (t & 1)*(NB*DEC);
        for (int i = tid; i < NB*128; i += 256) {
            int bb = i >> 7, c = i & 127;
            hs[bb*HP + c] = __ldcg(((const float4*)hsrc) + bb*128 + c);
        }
        __syncthreads();

        float acc = xw[(long)t*(G4*NB) + j*NB + b];
        const float4* wr = ws + jl*WP;
        const float4* hr = hs + b*HP;
        #pragma unroll 4
        for (int k4 = 0; k4 < 128; k4++) {
            float4 w4 = wr[k4];
            float4 h4 = hr[k4];
            acc += w4.x*h4.x + w4.y*h4.y + w4.z*h4.z + w4.w*h4.w;
        }
        gx[tid] = acc;
        __syncthreads();

        if (tid < 64) {
            float ig = sigf(gx[tid]);
            float fg = sigf(gx[64 + tid]);
            float gg = tanhf(gx[128 + tid]);
            float og = sigf(gx[192 + tid]);
            c_reg = fg*c_reg + ig*gg;
            float h = og * tanhf(c_reg);
            int ddl = tid >> 4, bb = tid & 15;
            int d = cta*4 + ddl;
            __stcg(&g_hbuf[((t+1) & 1)*(NB*DEC) + bb*DEC + d], h);
            out[bb*bstr + (long)t*tstr + d] = h;
        }
        grid_barrier();
    }
}

// ---------------- kernel 5: causal self-attention (CTA per (q,b)) ----------------
__global__ void __launch_bounds__(256) attn_kernel()
{
    __shared__ float hqs[512];
    __shared__ float sc[256];
    __shared__ float red[256];
    int q = blockIdx.x, b = blockIdx.y;
    int tid = threadIdx.x;
    int nk = q + 1;
    float* catb = g_cat + (long)b*(LSEQ*2*DEC);

    if (tid < 128)
        ((float4*)hqs)[tid] = ((const float4*)(catb + q*1024 + 512))[tid];
    __syncthreads();

    int w = tid >> 5, lane = tid & 31;
    for (int k = w; k < nk; k += 8) {
        const float4* hk = (const float4*)(catb + k*1024 + 512);
        float s = 0.f;
        #pragma unroll
        for (int i = 0; i < 4; i++) {
            float4 a = ((float4*)hqs)[lane + 32*i];
            float4 c = hk[lane + 32*i];
            s += a.x*c.x + a.y*c.y + a.z*c.z + a.w*c.w;
        }
        #pragma unroll
        for (int off = 16; off; off >>= 1) s += __shfl_xor_sync(0xffffffffu, s, off);
        if (lane == 0) sc[k] = s;
    }
    __syncthreads();

    float v = (tid < nk) ? sc[tid] : -INFINITY;
    red[tid] = v; __syncthreads();
    #pragma unroll
    for (int s = 128; s; s >>= 1) {
        if (tid < s) red[tid] = fmaxf(red[tid], red[tid+s]);
        __syncthreads();
    }
    float mx = red[0]; __syncthreads();
    float e = (tid < nk) ? __expf(v - mx) : 0.f;
    red[tid] = e; __syncthreads();
    #pragma unroll
    for (int s = 128; s; s >>= 1) {
        if (tid < s) red[tid] += red[tid+s];
        __syncthreads();
    }
    float inv = 1.f / red[0];
    __syncthreads();
    if (tid < nk) sc[tid] = e * inv;
    __syncthreads();

    float a0 = 0.f, a1 = 0.f;
    for (int k = 0; k < nk; k++) {
        float wk = sc[k];
        const float* hk = catb + k*1024 + 512;
        a0 += wk * hk[tid];
        a1 += wk * hk[tid + 256];
    }
    catb[q*1024 + tid]       = a0;
    catb[q*1024 + tid + 256] = a1;
}

// ---------------- kernel 6: fc2 single-pass tf32 tensor GEMM ----------------
// C[4096,32000] = A[4096,512] * B[32000,512]^T + bias, tf32 inputs (cvt.rna), fp32 acc
// CTA tile 128x128, k-stage 32 (4 k8 steps), cp.async double buffer, 8 warps (32x64)
#define TF_KS    32
#define TF_AST   36                        // smem row stride in floats (conflict-free)
#define TF_TILE  (128*TF_AST)              // floats per matrix tile
#define TF_SMEM  (2*2*TF_TILE*4)           // 73728 B

__device__ __forceinline__ unsigned f2tf32(float v)
{
    unsigned u;
    asm("cvt.rna.tf32.f32 %0, %1;" : "=r"(u) : "f"(v));
    return u;
}

__device__ __forceinline__ void mma_tf32(float* c, const unsigned* a, const unsigned* b)
{
    asm volatile(
        "mma.sync.aligned.m16n8k8.row.col.f32.tf32.tf32.f32 "
        "{%0,%1,%2,%3}, {%4,%5,%6,%7}, {%8,%9}, {%0,%1,%2,%3};\n"
        : "+f"(c[0]), "+f"(c[1]), "+f"(c[2]), "+f"(c[3])
        : "r"(a[0]), "r"(a[1]), "r"(a[2]), "r"(a[3]), "r"(b[0]), "r"(b[1]));
}

__global__ void __launch_bounds__(256, 2) fc2_tf32_kernel(
    const float* __restrict__ A, const float* __restrict__ B,
    const float* __restrict__ bias, float* __restrict__ C)
{
    extern __shared__ float smf[];
    const int tid  = threadIdx.x;
    const int lane = tid & 31;
    const int warp = tid >> 5;
    const int warp_m = warp >> 1;        // 0..3 -> rows 32*warp_m
    const int warp_n = warp & 1;         // 0..1 -> cols 64*warp_n
    const int m0 = blockIdx.y * 128;
    const int n0 = blockIdx.x * 128;
    const int g = lane >> 2;             // 0..7
    const int t = lane & 3;              // 0..3

    unsigned sbase = (unsigned)__cvta_generic_to_shared(smf);

    // cp.async one 32-K stage (A 128x32, B 128x32 fp32) into buffer `buf`
    auto issue_load = [&](int buf, int k0) {
        #pragma unroll
        for (int rep = 0; rep < 8; rep++) {
            int i   = tid + rep*256;       // 0..2047
            int mat = i >> 10;             // 0 = A, 1 = B
            int idx = i & 1023;
            int row = idx >> 3;            // 0..127
            int q   = idx & 7;             // 0..7 (16B chunks)
            unsigned daddr = sbase + ((buf*2 + mat)*TF_TILE + row*TF_AST + q*4)*4;
            const float* gsrc = (mat ? B + (long)(n0+row)*DEC
                                     : A + (long)(m0+row)*DEC) + k0 + q*4;
            asm volatile("cp.async.cg.shared.global [%0], [%1], 16;\n"
                         :: "r"(daddr), "l"(gsrc));
        }
        asm volatile("cp.async.commit_group;\n");
    };

    float acc[2][8][4];
    #pragma unroll
    for (int i = 0; i < 2; i++)
        #pragma unroll
        for (int j = 0; j < 8; j++)
            #pragma unroll
            for (int r = 0; r < 4; r++) acc[i][j][r] = 0.f;

    issue_load(0, 0);

    int buf = 0;
    for (int ks = 0; ks < DEC/TF_KS; ks++) {
        asm volatile("cp.async.wait_group 0;\n");
        __syncthreads();
        if (ks + 1 < DEC/TF_KS) issue_load(buf ^ 1, (ks+1)*TF_KS);

        const float* sA = smf + (buf*2 + 0)*TF_TILE;
        const float* sB = smf + (buf*2 + 1)*TF_TILE;

        #pragma unroll
        for (int k8 = 0; k8 < 4; k8++) {
            int kc = k8*8 + t;
            // A fragments (2 m16 tiles): a0..a3 per tile
            unsigned af[2][4];
            #pragma unroll
            for (int im = 0; im < 2; im++) {
                int rb = warp_m*32 + im*16 + g;
                af[im][0] = f2tf32(sA[rb*TF_AST + kc]);
                af[im][1] = f2tf32(sA[(rb+8)*TF_AST + kc]);
                af[im][2] = f2tf32(sA[rb*TF_AST + kc + 4]);
                af[im][3] = f2tf32(sA[(rb+8)*TF_AST + kc + 4]);
            }
            // B fragments (8 n8 tiles): b0,b1 per tile
            unsigned bf[8][2];
            #pragma unroll
            for (int in = 0; in < 8; in++) {
                int nc = warp_n*64 + in*8 + g;
                bf[in][0] = f2tf32(sB[nc*TF_AST + k8*8 + t]);
                bf[in][1] = f2tf32(sB[nc*TF_AST + k8*8 + t + 4]);
            }
            #pragma unroll
            for (int im = 0; im < 2; im++)
                #pragma unroll
                for (int in = 0; in < 8; in++)
                    mma_tf32(acc[im][in], af[im], bf[in]);
        }
        buf ^= 1;
        __syncthreads();
    }

    // epilogue: add bias, store fp32
    #pragma unroll
    for (int im = 0; im < 2; im++) {
        int row = m0 + warp_m*32 + im*16 + g;
        #pragma unroll
        for (int in = 0; in < 8; in++) {
            int col = n0 + warp_n*64 + in*8 + t*2;
            float b0 = bias[col], b1 = bias[col+1];
            float2 v0 = make_float2(acc[im][in][0] + b0, acc[im][in][1] + b1);
            float2 v1 = make_float2(acc[im][in][2] + b0, acc[im][in][3] + b1);
            *(float2*)(C + (long)row*NV + col)     = v0;
            *(float2*)(C + (long)(row+8)*NV + col) = v1;
        }
    }
}

// ---------------- launch ----------------
extern "C" void kernel_launch(void* const* d_in, const int* in_sizes, int n_in,
                              void* d_out, int out_size)
{
    const float* x       = (const float*)d_in[0];
    const int*   y       = (const int*)  d_in[1];
    const float* fc1_w   = (const float*)d_in[2];
    const float* fc1_b   = (const float*)d_in[3];
    const float* bn_g    = (const float*)d_in[4];
    const float* bn_b    = (const float*)d_in[5];
    const float* emb     = (const float*)d_in[6];
    const float* l1_Wih  = (const float*)d_in[7];
    const float* l1_Whh  = (const float*)d_in[8];
    const float* l1_bih  = (const float*)d_in[9];
    const float* l1_bhh  = (const float*)d_in[10];
    const float* attn_W  = (const float*)d_in[11];
    const float* dc_Wih  = (const float*)d_in[12];
    const float* dc_Whh  = (const float*)d_in[13];
    const float* dc_bih  = (const float*)d_in[14];
    const float* dc_bhh  = (const float*)d_in[15];
    const float* fc2_w   = (const float*)d_in[16];
    const float* fc2_b   = (const float*)d_in[17];
    float* out = (float*)d_out;

    float *p_seq, *p_xw, *p_cat, *p_attn, *p_h2;
    cudaGetSymbolAddress((void**)&p_seq,  g_seq);
    cudaGetSymbolAddress((void**)&p_xw,   g_xw);
    cudaGetSymbolAddress((void**)&p_cat,  g_cat);
    cudaGetSymbolAddress((void**)&p_attn, g_attn);
    cudaGetSymbolAddress((void**)&p_h2,   g_h2);

    int lstm_smem = (16*WP + 16*HP)*16 + 256*4;
    cudaFuncSetAttribute(lstm_kernel, cudaFuncAttributeMaxDynamicSharedMemorySize, lstm_smem);
    cudaFuncSetAttribute(fc2_tf32_kernel, cudaFuncAttributeMaxDynamicSharedMemorySize, TF_SMEM);

    // 1. fc1 + BN
    fc1_bn_kernel<<<1, 256>>>(x, fc1_w, fc1_b, bn_g, bn_b);
    // 2. embedding
    embed_kernel<<<NB*(LSEQ-1), 64>>>(y, emb);
    // 3. xw1 = seq @ l1_Wih^T + biases   (LSTM layout)
    sgemm_tn<1,false><<<dim3(G4/128, MROWS/128), 256>>>(
        p_seq, l1_Wih, l1_bih, l1_bhh, p_xw, MROWS, G4, EMB);
    // 4. LSTM 1  ->  g_cat[b][t][512:1024]
    lstm_kernel<<<LSTM_CTAS, 256, lstm_smem>>>(
        p_xw, l1_Whh, p_cat + 512, (long)LSEQ*2*DEC, (long)2*DEC);
    // 5. attention -> g_cat[b][t][0:512]
    attn_kernel<<<dim3(LSEQ, NB), 256>>>();
    // 6. attn = tanh(cat @ attn_W^T)
    sgemm_tn<0,true><<<dim3(DEC/128, MROWS/128), 256>>>(
        p_cat, attn_W, nullptr, nullptr, p_attn, MROWS, DEC, 2*DEC);
    // 7. xw2 = attn @ dc_Wih^T + biases  (LSTM layout)
    sgemm_tn<1,false><<<dim3(G4/128, MROWS/128), 256>>>(
        p_attn, dc_Wih, dc_bih, dc_bhh, p_xw, MROWS, G4, DEC);
    // 8. LSTM 2 -> g_h2[m][d]
    lstm_kernel<<<LSTM_CTAS, 256, lstm_smem>>>(
        p_xw, dc_Whh, p_h2, (long)LSEQ*DEC, (long)DEC);
    // 9. fc2 single-pass tf32 tensor GEMM -> d_out
    fc2_tf32_kernel<<<dim3(NV/128, MROWS/128), 256, TF_SMEM>>>(
        p_h2, fc2_w, fc2_b, out);
}

// round 9
// speedup vs baseline: 1.0876x; 1.0304x over previous
#include <cuda_runtime.h>
#include <cuda_bf16.h>
#include <math.h>

// ---------------- problem constants ----------------
#define NB   16          // batch
#define LSEQ 256         // sequence length (TY+1)
#define ENC  512
#define EMB  256
#define DEC  512
#define NV   32000
#define G4   2048        // 4*DEC
#define MROWS 4096       // NB*LSEQ

// ---------------- scratch (__device__ globals; no allocs) ----------------
__device__ float g_seq [NB*LSEQ*EMB];        //  4 MB  [b][t][EMB]
__device__ float g_xw  [LSEQ*G4*NB];         // 32 MB  [t][j][b]
__device__ float g_cat [NB*LSEQ*2*DEC];      // 16 MB  [b][t][ mix(512) | h1(512) ]
__device__ float g_attn[MROWS*DEC];          //  8 MB  [m][512]
__device__ float g_h2  [MROWS*DEC];          //  8 MB  [m][512]
__device__ float g_hbuf[2*NB*DEC];           // h double buffer
// hierarchical barrier state (zero-initialized; every barrier self-resets)
__device__ unsigned          g_leaf[16*32];  // 16 counters, 128B apart
__device__ unsigned          g_root;
__device__ volatile unsigned g_gen;

__device__ __forceinline__ float sigf(float x){ return 1.0f/(1.0f+__expf(-x)); }

// ---------------- hierarchical grid barrier (128 CTAs: 16 leaves x 8) ----------------
__device__ __forceinline__ void grid_barrier128(int cta)
{
    __syncthreads();
    if (threadIdx.x == 0) {
        __threadfence();
        unsigned gen = g_gen;
        unsigned leaf = (unsigned)cta & 15u;
        if (atomicAdd(&g_leaf[leaf*32], 1u) == 7u) {
            g_leaf[leaf*32] = 0u;
            __threadfence();
            if (atomicAdd(&g_root, 1u) == 15u) {
                g_root = 0u;
                __threadfence();
                g_gen = gen + 1u;
            } else {
                while (g_gen == gen) { }
            }
        } else {
            while (g_gen == gen) { }
        }
    }
    __syncthreads();
}

// ---------------- kernel 1: fc1 + BatchNorm (batch stats) -> seq[:,0,:] ----------------
__global__ void __launch_bounds__(256) fc1_bn_kernel(
    const float* __restrict__ x,     // [16,512]
    const float* __restrict__ w,     // [256,512]
    const float* __restrict__ bias,  // [256]
    const float* __restrict__ gam,   // [256]
    const float* __restrict__ bet)   // [256]
{
    __shared__ float xs[NB*ENC];     // 32 KB
    int tid = threadIdx.x;
    for (int i = tid; i < NB*ENC/4; i += 256)
        ((float4*)xs)[i] = ((const float4*)x)[i];
    __syncthreads();

    int j = tid;                     // one feature per thread (EMB == 256)
    float f[NB];
    #pragma unroll
    for (int b = 0; b < NB; b++) f[b] = bias[j];

    const float4* w4 = (const float4*)(w + j*ENC);
    for (int k4 = 0; k4 < ENC/4; k4++) {
        float4 ww = w4[k4];
        #pragma unroll
        for (int b = 0; b < NB; b++) {
            float4 xx = ((float4*)xs)[b*(ENC/4) + k4];
            f[b] += ww.x*xx.x + ww.y*xx.y + ww.z*xx.z + ww.w*xx.w;
        }
    }
    float mu = 0.f;
    #pragma unroll
    for (int b = 0; b < NB; b++) mu += f[b];
    mu *= (1.0f/NB);
    float var = 0.f;
    #pragma unroll
    for (int b = 0; b < NB; b++) { float d = f[b]-mu; var += d*d; }
    var *= (1.0f/NB);
    float s = rsqrtf(var + 1e-5f) * gam[j];
    float bb = bet[j];
    #pragma unroll
    for (int b = 0; b < NB; b++)
        g_seq[b*(LSEQ*EMB) + j] = (f[b]-mu)*s + bb;   // t = 0
}

// ---------------- kernel 2: embedding gather -> seq[:,1:,:] ----------------
__global__ void embed_kernel(const int* __restrict__ y,      // [16,255]
                             const float* __restrict__ emb)  // [32000,256]
{
    int blk = blockIdx.x;            // 16*255 blocks
    int b = blk / (LSEQ-1), t = blk % (LSEQ-1);
    int row = y[b*(LSEQ-1) + t];
    const float4* src = (const float4*)(emb + (long)row*EMB);
    float4* dst = (float4*)(g_seq + b*(LSEQ*EMB) + (t+1)*EMB);
    dst[threadIdx.x] = src[threadIdx.x];   // 64 threads * float4 = 256 floats
}

// ---------------- tf32 helpers ----------------
__device__ __forceinline__ unsigned f2tf32(float v)
{
    unsigned u;
    asm("cvt.rna.tf32.f32 %0, %1;" : "=r"(u) : "f"(v));
    return u;
}

__device__ __forceinline__ void mma_tf32(float* c, const unsigned* a, const unsigned* b)
{
    asm volatile(
        "mma.sync.aligned.m16n8k8.row.col.f32.tf32.tf32.f32 "
        "{%0,%1,%2,%3}, {%4,%5,%6,%7}, {%8,%9}, {%0,%1,%2,%3};\n"
        : "+f"(c[0]), "+f"(c[1]), "+f"(c[2]), "+f"(c[3])
        : "r"(a[0]), "r"(a[1]), "r"(a[2]), "r"(a[3]), "r"(b[0]), "r"(b[1]));
}

#define TF_KS    32
#define TF_AST   36                        // smem row stride in floats (conflict-free)
#define TF_TILE  (128*TF_AST)              // floats per matrix tile
#define TF_SMEM  (2*2*TF_TILE*4)           // 73728 B

// ---------------- kernel 3: generic tf32 GEMM  C = A[M,K] * B[N,K]^T (+bias) ----------------
// MODE 0: C[m*Cld+n] (+tanh opt);  MODE 1: C[t*(N*16) + n*16 + b], m = b*256+t
template<int MODE, bool DOTANH>
__global__ void __launch_bounds__(256, 2) gemm_tf32(
    const float* __restrict__ A, const float* __restrict__ B,
    const float* __restrict__ bias0, const float* __restrict__ bias1,
    float* __restrict__ C, int N, int K, int Cld)
{
    extern __shared__ float smf[];
    const int tid  = threadIdx.x;
    const int lane = tid & 31;
    const int warp = tid >> 5;
    const int warp_m = warp >> 1;
    const int warp_n = warp & 1;
    const int m0 = blockIdx.y * 128;
    const int n0 = blockIdx.x * 128;
    const int g = lane >> 2;
    const int t = lane & 3;

    unsigned sbase = (unsigned)__cvta_generic_to_shared(smf);

    auto issue_load = [&](int buf, int k0) {
        #pragma unroll
        for (int rep = 0; rep < 8; rep++) {
            int i   = tid + rep*256;
            int mat = i >> 10;
            int idx = i & 1023;
            int row = idx >> 3;
            int q   = idx & 7;
            unsigned daddr = sbase + ((buf*2 + mat)*TF_TILE + row*TF_AST + q*4)*4;
            const float* gsrc = (mat ? B + (long)(n0+row)*K
                                     : A + (long)(m0+row)*K) + k0 + q*4;
            asm volatile("cp.async.cg.shared.global [%0], [%1], 16;\n"
                         :: "r"(daddr), "l"(gsrc));
        }
        asm volatile("cp.async.commit_group;\n");
    };

    float acc[2][8][4];
    #pragma unroll
    for (int i = 0; i < 2; i++)
        #pragma unroll
        for (int j = 0; j < 8; j++)
            #pragma unroll
            for (int r = 0; r < 4; r++) acc[i][j][r] = 0.f;

    issue_load(0, 0);

    int nst = K / TF_KS;
    int buf = 0;
    for (int ks = 0; ks < nst; ks++) {
        asm volatile("cp.async.wait_group 0;\n");
        __syncthreads();
        if (ks + 1 < nst) issue_load(buf ^ 1, (ks+1)*TF_KS);

        const float* sA = smf + (buf*2 + 0)*TF_TILE;
        const float* sB = smf + (buf*2 + 1)*TF_TILE;

        #pragma unroll
        for (int k8 = 0; k8 < 4; k8++) {
            int kc = k8*8 + t;
            unsigned af[2][4];
            #pragma unroll
            for (int im = 0; im < 2; im++) {
                int rb = warp_m*32 + im*16 + g;
                af[im][0] = f2tf32(sA[rb*TF_AST + kc]);
                af[im][1] = f2tf32(sA[(rb+8)*TF_AST + kc]);
                af[im][2] = f2tf32(sA[rb*TF_AST + kc + 4]);
                af[im][3] = f2tf32(sA[(rb+8)*TF_AST + kc + 4]);
            }
            unsigned bf[8][2];
            #pragma unroll
            for (int in = 0; in < 8; in++) {
                int nc = warp_n*64 + in*8 + g;
                bf[in][0] = f2tf32(sB[nc*TF_AST + kc]);
                bf[in][1] = f2tf32(sB[nc*TF_AST + kc + 4]);
            }
            #pragma unroll
            for (int im = 0; im < 2; im++)
                #pragma unroll
                for (int in = 0; in < 8; in++)
                    mma_tf32(acc[im][in], af[im], bf[in]);
        }
        buf ^= 1;
        __syncthreads();
    }

    #pragma unroll
    for (int im = 0; im < 2; im++) {
        int row = m0 + warp_m*32 + im*16 + g;
        #pragma unroll
        for (int in = 0; in < 8; in++) {
            int col = n0 + warp_n*64 + in*8 + t*2;
            float bs0 = 0.f, bs1 = 0.f;
            if (bias0) { bs0 += bias0[col]; bs1 += bias0[col+1]; }
            if (bias1) { bs0 += bias1[col]; bs1 += bias1[col+1]; }
            float v00 = acc[im][in][0] + bs0, v01 = acc[im][in][1] + bs1;
            float v10 = acc[im][in][2] + bs0, v11 = acc[im][in][3] + bs1;
            if (DOTANH) { v00 = tanhf(v00); v01 = tanhf(v01);
                          v10 = tanhf(v10); v11 = tanhf(v11); }
            if (MODE == 0) {
                *(float2*)(C + (long)row*Cld + col)     = make_float2(v00, v01);
                *(float2*)(C + (long)(row+8)*Cld + col) = make_float2(v10, v11);
            } else {
                int b0 = row >> 8, t0 = row & 255;
                int b1 = (row+8) >> 8, t1 = (row+8) & 255;
                C[(long)t0*(N*NB) + col*NB + b0]     = v00;
                C[(long)t0*(N*NB) + (col+1)*NB + b0] = v01;
                C[(long)t1*(N*NB) + col*NB + b1]     = v10;
                C[(long)t1*(N*NB) + (col+1)*NB + b1] = v11;
            }
        }
    }
}

// ---------------- kernel 4: persistent LSTM (128 CTAs) ----------------
#define LSTM_CTAS 128
#define WP 130   // smem row stride in float4
#define HP 130

__global__ void __launch_bounds__(256, 1) lstm_kernel(
    const float* __restrict__ xw,
    const float* __restrict__ Whh,   // [2048,512]
    float* __restrict__ out, long bstr, long tstr)
{
    extern __shared__ float4 smem[];
    float4* ws = smem;               // 16*WP
    float4* hs = smem + 16*WP;       // 16*HP
    float*  gx = (float*)(smem + 16*WP + 16*HP);   // 256 floats

    int tid = threadIdx.x, cta = blockIdx.x;
    int gate = tid >> 6, dl = (tid >> 4) & 3, b = tid & 15;
    int jl = gate*4 + dl;
    int j  = gate*512 + cta*4 + dl;

    for (int i = tid; i < 16*128; i += 256) {
        int r = i >> 7, c = i & 127;
        int jj = (r >> 2)*512 + cta*4 + (r & 3);
        ws[r*WP + c] = ((const float4*)Whh)[jj*128 + c];
    }
    for (int i = cta*256 + tid; i < NB*DEC; i += LSTM_CTAS*256)
        g_hbuf[i] = 0.f;

    float c_reg = 0.f;
    grid_barrier128(cta);

    for (int t = 0; t < LSEQ; t++) {
        const float* hsrc = g_hbuf + (t & 1)*(NB*DEC);
        for (int i = tid; i < NB*128; i += 256) {
            int bb = i >> 7, c = i & 127;
            hs[bb*HP + c] = __ldcg(((const float4*)hsrc) + bb*128 + c);
        }
        __syncthreads();

        // 4-way split accumulators; xw load off the dependency chain
        float xwv = xw[(long)t*(G4*NB) + j*NB + b];
        const float4* wr = ws + jl*WP;
        const float4* hr = hs + b*HP;
        float a0 = 0.f, a1 = 0.f, a2 = 0.f, a3 = 0.f;
        #pragma unroll 4
        for (int k4 = 0; k4 < 128; k4++) {
            float4 w4 = wr[k4];
            float4 h4 = hr[k4];
            a0 += w4.x*h4.x; a1 += w4.y*h4.y;
            a2 += w4.z*h4.z; a3 += w4.w*h4.w;
        }
        gx[tid] = xwv + ((a0 + a1) + (a2 + a3));
        __syncthreads();

        if (tid < 64) {
            float ig = sigf(gx[tid]);
            float fg = sigf(gx[64 + tid]);
            float gg = tanhf(gx[128 + tid]);
            float og = sigf(gx[192 + tid]);
            c_reg = fg*c_reg + ig*gg;
            float h = og * tanhf(c_reg);
            int ddl = tid >> 4, bb = tid & 15;
            int d = cta*4 + ddl;
            __stcg(&g_hbuf[((t+1) & 1)*(NB*DEC) + bb*DEC + d], h);
            out[bb*bstr + (long)t*tstr + d] = h;
        }
        grid_barrier128(cta);
    }
}

// ---------------- kernel 5: causal self-attention (CTA per (q,b)) ----------------
__global__ void __launch_bounds__(256) attn_kernel()
{
    __shared__ float hqs[512];
    __shared__ float sc[256];
    __shared__ float red[256];
    int q = blockIdx.x, b = blockIdx.y;
    int tid = threadIdx.x;
    int nk = q + 1;
    float* catb = g_cat + (long)b*(LSEQ*2*DEC);

    if (tid < 128)
        ((float4*)hqs)[tid] = ((const float4*)(catb + q*1024 + 512))[tid];
    __syncthreads();

    int w = tid >> 5, lane = tid & 31;
    for (int k = w; k < nk; k += 8) {
        const float4* hk = (const float4*)(catb + k*1024 + 512);
        float s = 0.f;
        #pragma unroll
        for (int i = 0; i < 4; i++) {
            float4 a = ((float4*)hqs)[lane + 32*i];
            float4 c = hk[lane + 32*i];
            s += a.x*c.x + a.y*c.y + a.z*c.z + a.w*c.w;
        }
        #pragma unroll
        for (int off = 16; off; off >>= 1) s += __shfl_xor_sync(0xffffffffu, s, off);
        if (lane == 0) sc[k] = s;
    }
    __syncthreads();

    float v = (tid < nk) ? sc[tid] : -INFINITY;
    red[tid] = v; __syncthreads();
    #pragma unroll
    for (int s = 128; s; s >>= 1) {
        if (tid < s) red[tid] = fmaxf(red[tid], red[tid+s]);
        __syncthreads();
    }
    float mx = red[0]; __syncthreads();
    float e = (tid < nk) ? __expf(v - mx) : 0.f;
    red[tid] = e; __syncthreads();
    #pragma unroll
    for (int s = 128; s; s >>= 1) {
        if (tid < s) red[tid] += red[tid+s];
        __syncthreads();
    }
    float inv = 1.f / red[0];
    __syncthreads();
    if (tid < nk) sc[tid] = e * inv;
    __syncthreads();

    float a0 = 0.f, a1 = 0.f;
    for (int k = 0; k < nk; k++) {
        float wk = sc[k];
        const float* hk = catb + k*1024 + 512;
        a0 += wk * hk[tid];
        a1 += wk * hk[tid + 256];
    }
    catb[q*1024 + tid]       = a0;
    catb[q*1024 + tid + 256] = a1;
}

// ---------------- kernel 6: fc2 single-pass tf32 tensor GEMM (proven) ----------------
__global__ void __launch_bounds__(256, 2) fc2_tf32_kernel(
    const float* __restrict__ A, const float* __restrict__ B,
    const float* __restrict__ bias, float* __restrict__ C)
{
    extern __shared__ float smf[];
    const int tid  = threadIdx.x;
    const int lane = tid & 31;
    const int warp = tid >> 5;
    const int warp_m = warp >> 1;
    const int warp_n = warp & 1;
    const int m0 = blockIdx.y * 128;
    const int n0 = blockIdx.x * 128;
    const int g = lane >> 2;
    const int t = lane & 3;

    unsigned sbase = (unsigned)__cvta_generic_to_shared(smf);

    auto issue_load = [&](int buf, int k0) {
        #pragma unroll
        for (int rep = 0; rep < 8; rep++) {
            int i   = tid + rep*256;
            int mat = i >> 10;
            int idx = i & 1023;
            int row = idx >> 3;
            int q   = idx & 7;
            unsigned daddr = sbase + ((buf*2 + mat)*TF_TILE + row*TF_AST + q*4)*4;
            const float* gsrc = (mat ? B + (long)(n0+row)*DEC
                                     : A + (long)(m0+row)*DEC) + k0 + q*4;
            asm volatile("cp.async.cg.shared.global [%0], [%1], 16;\n"
                         :: "r"(daddr), "l"(gsrc));
        }
        asm volatile("cp.async.commit_group;\n");
    };

    float acc[2][8][4];
    #pragma unroll
    for (int i = 0; i < 2; i++)
        #pragma unroll
        for (int j = 0; j < 8; j++)
            #pragma unroll
            for (int r = 0; r < 4; r++) acc[i][j][r] = 0.f;

    issue_load(0, 0);

    int buf = 0;
    for (int ks = 0; ks < DEC/TF_KS; ks++) {
        asm volatile("cp.async.wait_group 0;\n");
        __syncthreads();
        if (ks + 1 < DEC/TF_KS) issue_load(buf ^ 1, (ks+1)*TF_KS);

        const float* sA = smf + (buf*2 + 0)*TF_TILE;
        const float* sB = smf + (buf*2 + 1)*TF_TILE;

        #pragma unroll
        for (int k8 = 0; k8 < 4; k8++) {
            int kc = k8*8 + t;
            unsigned af[2][4];
            #pragma unroll
            for (int im = 0; im < 2; im++) {
                int rb = warp_m*32 + im*16 + g;
                af[im][0] = f2tf32(sA[rb*TF_AST + kc]);
                af[im][1] = f2tf32(sA[(rb+8)*TF_AST + kc]);
                af[im][2] = f2tf32(sA[rb*TF_AST + kc + 4]);
                af[im][3] = f2tf32(sA[(rb+8)*TF_AST + kc + 4]);
            }
            unsigned bf[8][2];
            #pragma unroll
            for (int in = 0; in < 8; in++) {
                int nc = warp_n*64 + in*8 + g;
                bf[in][0] = f2tf32(sB[nc*TF_AST + kc]);
                bf[in][1] = f2tf32(sB[nc*TF_AST + kc + 4]);
            }
            #pragma unroll
            for (int im = 0; im < 2; im++)
                #pragma unroll
                for (int in = 0; in < 8; in++)
                    mma_tf32(acc[im][in], af[im], bf[in]);
        }
        buf ^= 1;
        __syncthreads();
    }

    #pragma unroll
    for (int im = 0; im < 2; im++) {
        int row = m0 + warp_m*32 + im*16 + g;
        #pragma unroll
        for (int in = 0; in < 8; in++) {
            int col = n0 + warp_n*64 + in*8 + t*2;
            float b0 = bias[col], b1 = bias[col+1];
            float2 v0 = make_float2(acc[im][in][0] + b0, acc[im][in][1] + b1);
            float2 v1 = make_float2(acc[im][in][2] + b0, acc[im][in][3] + b1);
            *(float2*)(C + (long)row*NV + col)     = v0;
            *(float2*)(C + (long)(row+8)*NV + col) = v1;
        }
    }
}

// ---------------- launch ----------------
extern "C" void kernel_launch(void* const* d_in, const int* in_sizes, int n_in,
                              void* d_out, int out_size)
{
    const float* x       = (const float*)d_in[0];
    const int*   y       = (const int*)  d_in[1];
    const float* fc1_w   = (const float*)d_in[2];
    const float* fc1_b   = (const float*)d_in[3];
    const float* bn_g    = (const float*)d_in[4];
    const float* bn_b    = (const float*)d_in[5];
    const float* emb     = (const float*)d_in[6];
    const float* l1_Wih  = (const float*)d_in[7];
    const float* l1_Whh  = (const float*)d_in[8];
    const float* l1_bih  = (const float*)d_in[9];
    const float* l1_bhh  = (const float*)d_in[10];
    const float* attn_W  = (const float*)d_in[11];
    const float* dc_Wih  = (const float*)d_in[12];
    const float* dc_Whh  = (const float*)d_in[13];
    const float* dc_bih  = (const float*)d_in[14];
    const float* dc_bhh  = (const float*)d_in[15];
    const float* fc2_w   = (const float*)d_in[16];
    const float* fc2_b   = (const float*)d_in[17];
    float* out = (float*)d_out;

    float *p_seq, *p_xw, *p_cat, *p_attn, *p_h2;
    cudaGetSymbolAddress((void**)&p_seq,  g_seq);
    cudaGetSymbolAddress((void**)&p_xw,   g_xw);
    cudaGetSymbolAddress((void**)&p_cat,  g_cat);
    cudaGetSymbolAddress((void**)&p_attn, g_attn);
    cudaGetSymbolAddress((void**)&p_h2,   g_h2);

    int lstm_smem = (16*WP + 16*HP)*16 + 256*4;
    cudaFuncSetAttribute(lstm_kernel, cudaFuncAttributeMaxDynamicSharedMemorySize, lstm_smem);
    cudaFuncSetAttribute(fc2_tf32_kernel, cudaFuncAttributeMaxDynamicSharedMemorySize, TF_SMEM);
    cudaFuncSetAttribute(gemm_tf32<1,false>, cudaFuncAttributeMaxDynamicSharedMemorySize, TF_SMEM);
    cudaFuncSetAttribute(gemm_tf32<0,true>,  cudaFuncAttributeMaxDynamicSharedMemorySize, TF_SMEM);

    // 1. fc1 + BN
    fc1_bn_kernel<<<1, 256>>>(x, fc1_w, fc1_b, bn_g, bn_b);
    // 2. embedding
    embed_kernel<<<NB*(LSEQ-1), 64>>>(y, emb);
    // 3. xw1 = seq @ l1_Wih^T + biases   (tf32, LSTM layout)
    gemm_tf32<1,false><<<dim3(G4/128, MROWS/128), 256, TF_SMEM>>>(
        p_seq, l1_Wih, l1_bih, l1_bhh, p_xw, G4, EMB, 0);
    // 4. LSTM 1  ->  g_cat[b][t][512:1024]
    lstm_kernel<<<LSTM_CTAS, 256, lstm_smem>>>(
        p_xw, l1_Whh, p_cat + 512, (long)LSEQ*2*DEC, (long)2*DEC);
    // 5. attention -> g_cat[b][t][0:512]
    attn_kernel<<<dim3(LSEQ, NB), 256>>>();
    // 6. attn = tanh(cat @ attn_W^T)   (tf32)
    gemm_tf32<0,true><<<dim3(DEC/128, MROWS/128), 256, TF_SMEM>>>(
        p_cat, attn_W, nullptr, nullptr, p_attn, DEC, 2*DEC, DEC);
    // 7. xw2 = attn @ dc_Wih^T + biases (tf32, LSTM layout)
    gemm_tf32<1,false><<<dim3(G4/128, MROWS/128), 256, TF_SMEM>>>(
        p_attn, dc_Wih, dc_bih, dc_bhh, p_xw, G4, DEC, 0);
    // 8. LSTM 2 -> g_h2[m][d]
    lstm_kernel<<<LSTM_CTAS, 256, lstm_smem>>>(
        p_xw, dc_Whh, p_h2, (long)LSEQ*DEC, (long)DEC);
    // 9. fc2 single-pass tf32 tensor GEMM -> d_out
    fc2_tf32_kernel<<<dim3(NV/128, MROWS/128), 256, TF_SMEM>>>(
        p_h2, fc2_w, fc2_b, out);
}

// round 11
// speedup vs baseline: 1.0898x; 1.0021x over previous
#include <cuda_runtime.h>
#include <cuda_bf16.h>
#include <math.h>

// ---------------- problem constants ----------------
#define NB   16          // batch
#define LSEQ 256         // sequence length (TY+1)
#define ENC  512
#define EMB  256
#define DEC  512
#define NV   32000
#define G4   2048        // 4*DEC
#define MROWS 4096       // NB*LSEQ

// ---------------- scratch (__device__ globals; no allocs) ----------------
__device__ float g_seq [NB*LSEQ*EMB];        //  4 MB  [b][t][EMB]
__device__ float g_xw  [LSEQ*G4*NB];         // 32 MB  [t][j][b]
__device__ float g_cat [NB*LSEQ*2*DEC];      // 16 MB  [b][t][ mix(512) | h1(512) ]
__device__ float g_attn[MROWS*DEC];          //  8 MB  [m][512]
__device__ float g_h2  [MROWS*DEC];          //  8 MB  [m][512]
// h double buffer, TRANSPOSED layout: word = q*2048 + d*4 + br  (b = 4q+br)
__device__ float g_hT  [2*NB*DEC];
// hierarchical barrier state (zero-initialized; every barrier self-resets)
__device__ unsigned          g_leaf[16*32];  // 16 counters, 128B apart
__device__ unsigned          g_root;
__device__ volatile unsigned g_gen;

__device__ __forceinline__ float sigf(float x){ return 1.0f/(1.0f+__expf(-x)); }

// ---------------- hierarchical grid barrier (128 CTAs: 16 leaves x 8) ----------------
__device__ __forceinline__ void grid_barrier128(int cta)
{
    __syncthreads();
    if (threadIdx.x == 0) {
        __threadfence();
        unsigned gen = g_gen;
        unsigned leaf = (unsigned)cta & 15u;
        if (atomicAdd(&g_leaf[leaf*32], 1u) == 7u) {
            g_leaf[leaf*32] = 0u;
            __threadfence();
            if (atomicAdd(&g_root, 1u) == 15u) {
                g_root = 0u;
                __threadfence();
                g_gen = gen + 1u;
            } else {
                while (g_gen == gen) { }
            }
        } else {
            while (g_gen == gen) { }
        }
    }
    __syncthreads();
}

// ---------------- kernel 1: fc1 + BatchNorm (batch stats) -> seq[:,0,:] ----------------
__global__ void __launch_bounds__(256) fc1_bn_kernel(
    const float* __restrict__ x,     // [16,512]
    const float* __restrict__ w,     // [256,512]
    const float* __restrict__ bias,  // [256]
    const float* __restrict__ gam,   // [256]
    const float* __restrict__ bet)   // [256]
{
    __shared__ float xs[NB*ENC];     // 32 KB
    int tid = threadIdx.x;
    for (int i = tid; i < NB*ENC/4; i += 256)
        ((float4*)xs)[i] = ((const float4*)x)[i];
    __syncthreads();

    int j = tid;                     // one feature per thread (EMB == 256)
    float f[NB];
    #pragma unroll
    for (int b = 0; b < NB; b++) f[b] = bias[j];

    const float4* w4 = (const float4*)(w + j*ENC);
    for (int k4 = 0; k4 < ENC/4; k4++) {
        float4 ww = w4[k4];
        #pragma unroll
        for (int b = 0; b < NB; b++) {
            float4 xx = ((float4*)xs)[b*(ENC/4) + k4];
            f[b] += ww.x*xx.x + ww.y*xx.y + ww.z*xx.z + ww.w*xx.w;
        }
    }
    float mu = 0.f;
    #pragma unroll
    for (int b = 0; b < NB; b++) mu += f[b];
    mu *= (1.0f/NB);
    float var = 0.f;
    #pragma unroll
    for (int b = 0; b < NB; b++) { float d = f[b]-mu; var += d*d; }
    var *= (1.0f/NB);
    float s = rsqrtf(var + 1e-5f) * gam[j];
    float bb = bet[j];
    #pragma unroll
    for (int b = 0; b < NB; b++)
        g_seq[b*(LSEQ*EMB) + j] = (f[b]-mu)*s + bb;   // t = 0
}

// ---------------- kernel 2: embedding gather -> seq[:,1:,:] ----------------
__global__ void embed_kernel(const int* __restrict__ y,      // [16,255]
                             const float* __restrict__ emb)  // [32000,256]
{
    int blk = blockIdx.x;            // 16*255 blocks
    int b = blk / (LSEQ-1), t = blk % (LSEQ-1);
    int row = y[b*(LSEQ-1) + t];
    const float4* src = (const float4*)(emb + (long)row*EMB);
    float4* dst = (float4*)(g_seq + b*(LSEQ*EMB) + (t+1)*EMB);
    dst[threadIdx.x] = src[threadIdx.x];   // 64 threads * float4 = 256 floats
}

// ---------------- tf32 helpers ----------------
__device__ __forceinline__ unsigned f2tf32(float v)
{
    unsigned u;
    asm("cvt.rna.tf32.f32 %0, %1;" : "=r"(u) : "f"(v));
    return u;
}

__device__ __forceinline__ void mma_tf32(float* c, const unsigned* a, const unsigned* b)
{
    asm volatile(
        "mma.sync.aligned.m16n8k8.row.col.f32.tf32.tf32.f32 "
        "{%0,%1,%2,%3}, {%4,%5,%6,%7}, {%8,%9}, {%0,%1,%2,%3};\n"
        : "+f"(c[0]), "+f"(c[1]), "+f"(c[2]), "+f"(c[3])
        : "r"(a[0]), "r"(a[1]), "r"(a[2]), "r"(a[3]), "r"(b[0]), "r"(b[1]));
}

#define TF_KS    32
#define TF_AST   36                        // smem row stride in floats (conflict-free)
#define TF_TILE  (128*TF_AST)              // floats per matrix tile
#define TF_SMEM  (2*2*TF_TILE*4)           // 73728 B

// ---------------- kernel 3: generic tf32 GEMM  C = A[M,K] * B[N,K]^T (+bias) ----------------
// MODE 0: C[m*Cld+n] (+tanh opt);  MODE 1: C[t*(N*16) + n*16 + b], m = b*256+t
template<int MODE, bool DOTANH>
__global__ void __launch_bounds__(256, 2) gemm_tf32(
    const float* __restrict__ A, const float* __restrict__ B,
    const float* __restrict__ bias0, const float* __restrict__ bias1,
    float* __restrict__ C, int N, int K, int Cld)
{
    extern __shared__ float smf[];
    const int tid  = threadIdx.x;
    const int lane = tid & 31;
    const int warp = tid >> 5;
    const int warp_m = warp >> 1;
    const int warp_n = warp & 1;
    const int m0 = blockIdx.y * 128;
    const int n0 = blockIdx.x * 128;
    const int g = lane >> 2;
    const int t = lane & 3;

    unsigned sbase = (unsigned)__cvta_generic_to_shared(smf);

    auto issue_load = [&](int buf, int k0) {
        #pragma unroll
        for (int rep = 0; rep < 8; rep++) {
            int i   = tid + rep*256;
            int mat = i >> 10;
            int idx = i & 1023;
            int row = idx >> 3;
            int q   = idx & 7;
            unsigned daddr = sbase + ((buf*2 + mat)*TF_TILE + row*TF_AST + q*4)*4;
            const float* gsrc = (mat ? B + (long)(n0+row)*K
                                     : A + (long)(m0+row)*K) + k0 + q*4;
            asm volatile("cp.async.cg.shared.global [%0], [%1], 16;\n"
                         :: "r"(daddr), "l"(gsrc));
        }
        asm volatile("cp.async.commit_group;\n");
    };

    float acc[2][8][4];
    #pragma unroll
    for (int i = 0; i < 2; i++)
        #pragma unroll
        for (int j = 0; j < 8; j++)
            #pragma unroll
            for (int r = 0; r < 4; r++) acc[i][j][r] = 0.f;

    issue_load(0, 0);

    int nst = K / TF_KS;
    int buf = 0;
    for (int ks = 0; ks < nst; ks++) {
        asm volatile("cp.async.wait_group 0;\n");
        __syncthreads();
        if (ks + 1 < nst) issue_load(buf ^ 1, (ks+1)*TF_KS);

        const float* sA = smf + (buf*2 + 0)*TF_TILE;
        const float* sB = smf + (buf*2 + 1)*TF_TILE;

        #pragma unroll
        for (int k8 = 0; k8 < 4; k8++) {
            int kc = k8*8 + t;
            unsigned af[2][4];
            #pragma unroll
            for (int im = 0; im < 2; im++) {
                int rb = warp_m*32 + im*16 + g;
                af[im][0] = f2tf32(sA[rb*TF_AST + kc]);
                af[im][1] = f2tf32(sA[(rb+8)*TF_AST + kc]);
                af[im][2] = f2tf32(sA[rb*TF_AST + kc + 4]);
                af[im][3] = f2tf32(sA[(rb+8)*TF_AST + kc + 4]);
            }
            unsigned bf[8][2];
            #pragma unroll
            for (int in = 0; in < 8; in++) {
                int nc = warp_n*64 + in*8 + g;
                bf[in][0] = f2tf32(sB[nc*TF_AST + kc]);
                bf[in][1] = f2tf32(sB[nc*TF_AST + kc + 4]);
            }
            #pragma unroll
            for (int im = 0; im < 2; im++)
                #pragma unroll
                for (int in = 0; in < 8; in++)
                    mma_tf32(acc[im][in], af[im], bf[in]);
        }
        buf ^= 1;
        __syncthreads();
    }

    #pragma unroll
    for (int im = 0; im < 2; im++) {
        int row = m0 + warp_m*32 + im*16 + g;
        #pragma unroll
        for (int in = 0; in < 8; in++) {
            int col = n0 + warp_n*64 + in*8 + t*2;
            float bs0 = 0.f, bs1 = 0.f;
            if (bias0) { bs0 += bias0[col]; bs1 += bias0[col+1]; }
            if (bias1) { bs0 += bias1[col]; bs1 += bias1[col+1]; }
            float v00 = acc[im][in][0] + bs0, v01 = acc[im][in][1] + bs1;
            float v10 = acc[im][in][2] + bs0, v11 = acc[im][in][3] + bs1;
            if (DOTANH) { v00 = tanhf(v00); v01 = tanhf(v01);
                          v10 = tanhf(v10); v11 = tanhf(v11); }
            if (MODE == 0) {
                *(float2*)(C + (long)row*Cld + col)     = make_float2(v00, v01);
                *(float2*)(C + (long)(row+8)*Cld + col) = make_float2(v10, v11);
            } else {
                int b0 = row >> 8, t0 = row & 255;
                int b1 = (row+8) >> 8, t1 = (row+8) & 255;
                C[(long)t0*(N*NB) + col*NB + b0]     = v00;
                C[(long)t0*(N*NB) + (col+1)*NB + b0] = v01;
                C[(long)t1*(N*NB) + col*NB + b1]     = v10;
                C[(long)t1*(N*NB) + (col+1)*NB + b1] = v11;
            }
        }
    }
}

// ---------------- kernel 4: persistent LSTM (128 CTAs) ----------------
// h ring buffer transposed: word = q*2048 + d*4 + br  (b = 4q+br)
// writer: CTA's 64 h values land in 4 contiguous 64B segments.
// out values buffered in smem, dumped once at the end (no per-step scattered STG).
#define LSTM_CTAS 128
#define WP 130   // smem row stride in float4
#define HP 130

__global__ void __launch_bounds__(256, 1) lstm_kernel(
    const float* __restrict__ xw,
    const float* __restrict__ Whh,   // [2048,512]
    float* __restrict__ out, long bstr, long tstr)
{
    extern __shared__ float4 smem[];
    float4* ws = smem;                                  // 16*WP float4
    float4* hs = smem + 16*WP;                          // 16*HP float4
    float*  gx   = (float*)(smem + 16*WP + 16*HP);      // 256 floats
    float*  outb = gx + 256;                            // 16384 floats (64KB)

    int tid = threadIdx.x, cta = blockIdx.x;
    int gate = tid >> 6, dl = (tid >> 4) & 3, b = tid & 15;
    int jl = gate*4 + dl;
    int j  = gate*512 + cta*4 + dl;

    // stage this CTA's 16 Whh rows into smem (once)
    for (int i = tid; i < 16*128; i += 256) {
        int r = i >> 7, c = i & 127;
        int jj = (r >> 2)*512 + cta*4 + (r & 3);
        ws[r*WP + c] = ((const float4*)Whh)[jj*128 + c];
    }
    // zero h slot 0
    for (int i = cta*256 + tid; i < NB*DEC; i += LSTM_CTAS*256)
        g_hT[i] = 0.f;

    const int q    = tid >> 6;       // 0..3  (batch quad)
    const int dl0  = tid & 63;       // 0..63 (d low bits)
    float c_reg = 0.f;
    grid_barrier128(cta);

    for (int t = 0; t < LSEQ; t++) {
        // prefetch xw (independent of h)
        float xwv = xw[(long)t*(G4*NB) + j*NB + b];

        // stage h(t): global [q][d][br] -> smem hs[b][d], conflict-free transpose
        const float4* hsrc4 = (const float4*)(g_hT + (t & 1)*(NB*DEC));
        float* hsw = (float*)hs;
        #pragma unroll
        for (int r = 0; r < 8; r++) {
            int d = r*64 + dl0;
            float4 v = __ldcg(hsrc4 + q*512 + d);
            hsw[(4*q+0)*(HP*4) + d] = v.x;
            hsw[(4*q+1)*(HP*4) + d] = v.y;
            hsw[(4*q+2)*(HP*4) + d] = v.z;
            hsw[(4*q+3)*(HP*4) + d] = v.w;
        }
        __syncthreads();

        // 4-way split accumulators
        const float4* wr = ws + jl*WP;
        const float4* hr = hs + b*HP;
        float a0 = 0.f, a1 = 0.f, a2 = 0.f, a3 = 0.f;
        #pragma unroll 4
        for (int k4 = 0; k4 < 128; k4++) {
            float4 w4 = wr[k4];
            float4 h4 = hr[k4];
            a0 += w4.x*h4.x; a1 += w4.y*h4.y;
            a2 += w4.z*h4.z; a3 += w4.w*h4.w;
        }
        gx[tid] = xwv + ((a0 + a1) + (a2 + a3));
        __syncthreads();

        if (tid < 64) {
            float ig = sigf(gx[tid]);
            float fg = sigf(gx[64 + tid]);
            float gg = tanhf(gx[128 + tid]);
            float og = sigf(gx[192 + tid]);
            c_reg = fg*c_reg + ig*gg;
            float h = og * tanhf(c_reg);
            int ddl = tid >> 4, bb = tid & 15;
            // h -> transposed ring (4 contiguous 64B segments per CTA)
            __stcg(&g_hT[(((t+1) & 1))*(NB*DEC)
                         + (bb >> 2)*2048 + cta*16 + ddl*4 + (bb & 3)], h);
            // out -> smem buffer [t][bb][ddl]
            outb[t*64 + bb*4 + ddl] = h;
        }
        grid_barrier128(cta);
    }

    // final dump of out buffer (16K floats per CTA, float4 per (t,b))
    for (int i = tid; i < 4096; i += 256) {
        int tt = i >> 4, bb = i & 15;
        float4 v = ((const float4*)outb)[i];
        *(float4*)(out + bb*bstr + (long)tt*tstr + cta*4) = v;
    }
}

// ---------------- kernel 5: causal self-attention (CTA per (q,b)) ----------------
__global__ void __launch_bounds__(256) attn_kernel()
{
    __shared__ float hqs[512];
    __shared__ float sc[256];
    __shared__ float red[256];
    int q = blockIdx.x, b = blockIdx.y;
    int tid = threadIdx.x;
    int nk = q + 1;
    float* catb = g_cat + (long)b*(LSEQ*2*DEC);

    if (tid < 128)
        ((float4*)hqs)[tid] = ((const float4*)(catb + q*1024 + 512))[tid];
    __syncthreads();

    int w = tid >> 5, lane = tid & 31;
    for (int k = w; k < nk; k += 8) {
        const float4* hk = (const float4*)(catb + k*1024 + 512);
        float s = 0.f;
        #pragma unroll
        for (int i = 0; i < 4; i++) {
            float4 a = ((float4*)hqs)[lane + 32*i];
            float4 c = hk[lane + 32*i];
            s += a.x*c.x + a.y*c.y + a.z*c.z + a.w*c.w;
        }
        #pragma unroll
        for (int off = 16; off; off >>= 1) s += __shfl_xor_sync(0xffffffffu, s, off);
        if (lane == 0) sc[k] = s;
    }
    __syncthreads();

    float v = (tid < nk) ? sc[tid] : -INFINITY;
    red[tid] = v; __syncthreads();
    #pragma unroll
    for (int s = 128; s; s >>= 1) {
        if (tid < s) red[tid] = fmaxf(red[tid], red[tid+s]);
        __syncthreads();
    }
    float mx = red[0]; __syncthreads();
    float e = (tid < nk) ? __expf(v - mx) : 0.f;
    red[tid] = e; __syncthreads();
    #pragma unroll
    for (int s = 128; s; s >>= 1) {
        if (tid < s) red[tid] += red[tid+s];
        __syncthreads();
    }
    float inv = 1.f / red[0];
    __syncthreads();
    if (tid < nk) sc[tid] = e * inv;
    __syncthreads();

    float a0 = 0.f, a1 = 0.f;
    for (int k = 0; k < nk; k++) {
        float wk = sc[k];
        const float* hk = catb + k*1024 + 512;
        a0 += wk * hk[tid];
        a1 += wk * hk[tid + 256];
    }
    catb[q*1024 + tid]       = a0;
    catb[q*1024 + tid + 256] = a1;
}

// ---------------- kernel 6: fc2 single-pass tf32 tensor GEMM (proven) ----------------
__global__ void __launch_bounds__(256, 2) fc2_tf32_kernel(
    const float* __restrict__ A, const float* __restrict__ B,
    const float* __restrict__ bias, float* __restrict__ C)
{
    extern __shared__ float smf[];
    const int tid  = threadIdx.x;
    const int lane = tid & 31;
    const int warp = tid >> 5;
    const int warp_m = warp >> 1;
    const int warp_n = warp & 1;
    const int m0 = blockIdx.y * 128;
    const int n0 = blockIdx.x * 128;
    const int g = lane >> 2;
    const int t = lane & 3;

    unsigned sbase = (unsigned)__cvta_generic_to_shared(smf);

    auto issue_load = [&](int buf, int k0) {
        #pragma unroll
        for (int rep = 0; rep < 8; rep++) {
            int i   = tid + rep*256;
            int mat = i >> 10;
            int idx = i & 1023;
            int row = idx >> 3;
            int q   = idx & 7;
            unsigned daddr = sbase + ((buf*2 + mat)*TF_TILE + row*TF_AST + q*4)*4;
            const float* gsrc = (mat ? B + (long)(n0+row)*DEC
                                     : A + (long)(m0+row)*DEC) + k0 + q*4;
            asm volatile("cp.async.cg.shared.global [%0], [%1], 16;\n"
                         :: "r"(daddr), "l"(gsrc));
        }
        asm volatile("cp.async.commit_group;\n");
    };

    float acc[2][8][4];
    #pragma unroll
    for (int i = 0; i < 2; i++)
        #pragma unroll
        for (int j = 0; j < 8; j++)
            #pragma unroll
            for (int r = 0; r < 4; r++) acc[i][j][r] = 0.f;

    issue_load(0, 0);

    int buf = 0;
    for (int ks = 0; ks < DEC/TF_KS; ks++) {
        asm volatile("cp.async.wait_group 0;\n");
        __syncthreads();
        if (ks + 1 < DEC/TF_KS) issue_load(buf ^ 1, (ks+1)*TF_KS);

        const float* sA = smf + (buf*2 + 0)*TF_TILE;
        const float* sB = smf + (buf*2 + 1)*TF_TILE;

        #pragma unroll
        for (int k8 = 0; k8 < 4; k8++) {
            int kc = k8*8 + t;
            unsigned af[2][4];
            #pragma unroll
            for (int im = 0; im < 2; im++) {
                int rb = warp_m*32 + im*16 + g;
                af[im][0] = f2tf32(sA[rb*TF_AST + kc]);
                af[im][1] = f2tf32(sA[(rb+8)*TF_AST + kc]);
                af[im][2] = f2tf32(sA[rb*TF_AST + kc + 4]);
                af[im][3] = f2tf32(sA[(rb+8)*TF_AST + kc + 4]);
            }
            unsigned bf[8][2];
            #pragma unroll
            for (int in = 0; in < 8; in++) {
                int nc = warp_n*64 + in*8 + g;
                bf[in][0] = f2tf32(sB[nc*TF_AST + kc]);
                bf[in][1] = f2tf32(sB[nc*TF_AST + kc + 4]);
            }
            #pragma unroll
            for (int im = 0; im < 2; im++)
                #pragma unroll
                for (int in = 0; in < 8; in++)
                    mma_tf32(acc[im][in], af[im], bf[in]);
        }
        buf ^= 1;
        __syncthreads();
    }

    #pragma unroll
    for (int im = 0; im < 2; im++) {
        int row = m0 + warp_m*32 + im*16 + g;
        #pragma unroll
        for (int in = 0; in < 8; in++) {
            int col = n0 + warp_n*64 + in*8 + t*2;
            float b0 = bias[col], b1 = bias[col+1];
            float2 v0 = make_float2(acc[im][in][0] + b0, acc[im][in][1] + b1);
            float2 v1 = make_float2(acc[im][in][2] + b0, acc[im][in][3] + b1);
            *(float2*)(C + (long)row*NV + col)     = v0;
            *(float2*)(C + (long)(row+8)*NV + col) = v1;
        }
    }
}

// ---------------- launch ----------------
extern "C" void kernel_launch(void* const* d_in, const int* in_sizes, int n_in,
                              void* d_out, int out_size)
{
    const float* x       = (const float*)d_in[0];
    const int*   y       = (const int*)  d_in[1];
    const float* fc1_w   = (const float*)d_in[2];
    const float* fc1_b   = (const float*)d_in[3];
    const float* bn_g    = (const float*)d_in[4];
    const float* bn_b    = (const float*)d_in[5];
    const float* emb     = (const float*)d_in[6];
    const float* l1_Wih  = (const float*)d_in[7];
    const float* l1_Whh  = (const float*)d_in[8];
    const float* l1_bih  = (const float*)d_in[9];
    const float* l1_bhh  = (const float*)d_in[10];
    const float* attn_W  = (const float*)d_in[11];
    const float* dc_Wih  = (const float*)d_in[12];
    const float* dc_Whh  = (const float*)d_in[13];
    const float* dc_bih  = (const float*)d_in[14];
    const float* dc_bhh  = (const float*)d_in[15];
    const float* fc2_w   = (const float*)d_in[16];
    const float* fc2_b   = (const float*)d_in[17];
    float* out = (float*)d_out;

    float *p_seq, *p_xw, *p_cat, *p_attn, *p_h2;
    cudaGetSymbolAddress((void**)&p_seq,  g_seq);
    cudaGetSymbolAddress((void**)&p_xw,   g_xw);
    cudaGetSymbolAddress((void**)&p_cat,  g_cat);
    cudaGetSymbolAddress((void**)&p_attn, g_attn);
    cudaGetSymbolAddress((void**)&p_h2,   g_h2);

    int lstm_smem = (16*WP + 16*HP)*16 + 256*4 + 16384*4;   // ws+hs + gx + outb
    cudaFuncSetAttribute(lstm_kernel, cudaFuncAttributeMaxDynamicSharedMemorySize, lstm_smem);
    cudaFuncSetAttribute(fc2_tf32_kernel, cudaFuncAttributeMaxDynamicSharedMemorySize, TF_SMEM);
    cudaFuncSetAttribute(gemm_tf32<1,false>, cudaFuncAttributeMaxDynamicSharedMemorySize, TF_SMEM);
    cudaFuncSetAttribute(gemm_tf32<0,true>,  cudaFuncAttributeMaxDynamicSharedMemorySize, TF_SMEM);

    // 1. fc1 + BN
    fc1_bn_kernel<<<1, 256>>>(x, fc1_w, fc1_b, bn_g, bn_b);
    // 2. embedding
    embed_kernel<<<NB*(LSEQ-1), 64>>>(y, emb);
    // 3. xw1 = seq @ l1_Wih^T + biases   (tf32, LSTM layout)
    gemm_tf32<1,false><<<dim3(G4/128, MROWS/128), 256, TF_SMEM>>>(
        p_seq, l1_Wih, l1_bih, l1_bhh, p_xw, G4, EMB, 0);
    // 4. LSTM 1  ->  g_cat[b][t][512:1024]
    lstm_kernel<<<LSTM_CTAS, 256, lstm_smem>>>(
        p_xw, l1_Whh, p_cat + 512, (long)LSEQ*2*DEC, (long)2*DEC);
    // 5. attention -> g_cat[b][t][0:512]
    attn_kernel<<<dim3(LSEQ, NB), 256>>>();
    // 6. attn = tanh(cat @ attn_W^T)   (tf32)
    gemm_tf32<0,true><<<dim3(DEC/128, MROWS/128), 256, TF_SMEM>>>(
        p_cat, attn_W, nullptr, nullptr, p_attn, DEC, 2*DEC, DEC);
    // 7. xw2 = attn @ dc_Wih^T + biases (tf32, LSTM layout)
    gemm_tf32<1,false><<<dim3(G4/128, MROWS/128), 256, TF_SMEM>>>(
        p_attn, dc_Wih, dc_bih, dc_bhh, p_xw, G4, DEC, 0);
    // 8. LSTM 2 -> g_h2[m][d]
    lstm_kernel<<<LSTM_CTAS, 256, lstm_smem>>>(
        p_xw, dc_Whh, p_h2, (long)LSEQ*DEC, (long)DEC);
    // 9. fc2 single-pass tf32 tensor GEMM -> d_out
    fc2_tf32_kernel<<<dim3(NV/128, MROWS/128), 256, TF_SMEM>>>(
        p_h2, fc2_w, fc2_b, out);
}

// round 12
// speedup vs baseline: 1.7467x; 1.6027x over previous
#include <cuda_runtime.h>
#include <cuda_bf16.h>
#include <math.h>

// ---------------- problem constants ----------------
#define NB   16          // batch
#define LSEQ 256         // sequence length (TY+1)
#define ENC  512
#define EMB  256
#define DEC  512
#define NV   32000
#define G4   2048        // 4*DEC
#define MROWS 4096       // NB*LSEQ

// ---------------- scratch (__device__ globals; no allocs) ----------------
__device__ float g_seq [NB*LSEQ*EMB];        //  4 MB  [b][t][EMB]
__device__ float g_xw  [LSEQ*G4*NB];         // 32 MB  [t][j][b]
__device__ float g_cat [NB*LSEQ*2*DEC];      // 16 MB  [b][t][ mix(512) | h1(512) ]
__device__ float g_attn[MROWS*DEC];          //  8 MB  [m][512]
__device__ float g_h2  [MROWS*DEC];          //  8 MB  [m][512]
// h double buffer, TRANSPOSED layout: word = q*2048 + d*4 + br  (b = 4q+br)
__device__ float g_hT  [2*NB*DEC];
// hierarchical barrier state (zero-initialized; every barrier self-resets)
__device__ unsigned          g_leaf[16*32];  // 16 counters, 128B apart
__device__ unsigned          g_root;
__device__ volatile unsigned g_gen;

__device__ __forceinline__ float sigf(float x){ return 1.0f/(1.0f+__expf(-x)); }

// ---------------- hierarchical grid barrier (128 CTAs: 16 leaves x 8) ----------------
__device__ __forceinline__ void grid_barrier128(int cta)
{
    __syncthreads();
    if (threadIdx.x == 0) {
        __threadfence();
        unsigned gen = g_gen;
        unsigned leaf = (unsigned)cta & 15u;
        if (atomicAdd(&g_leaf[leaf*32], 1u) == 7u) {
            g_leaf[leaf*32] = 0u;
            __threadfence();
            if (atomicAdd(&g_root, 1u) == 15u) {
                g_root = 0u;
                __threadfence();
                g_gen = gen + 1u;
            } else {
                while (g_gen == gen) { }
            }
        } else {
            while (g_gen == gen) { }
        }
    }
    __syncthreads();
}

// ---------------- kernel 1: fc1 + BatchNorm (batch stats) -> seq[:,0,:] ----------------
__global__ void __launch_bounds__(256) fc1_bn_kernel(
    const float* __restrict__ x,     // [16,512]
    const float* __restrict__ w,     // [256,512]
    const float* __restrict__ bias,  // [256]
    const float* __restrict__ gam,   // [256]
    const float* __restrict__ bet)   // [256]
{
    __shared__ float xs[NB*ENC];     // 32 KB
    int tid = threadIdx.x;
    for (int i = tid; i < NB*ENC/4; i += 256)
        ((float4*)xs)[i] = ((const float4*)x)[i];
    __syncthreads();

    int j = tid;                     // one feature per thread (EMB == 256)
    float f[NB];
    #pragma unroll
    for (int b = 0; b < NB; b++) f[b] = bias[j];

    const float4* w4 = (const float4*)(w + j*ENC);
    for (int k4 = 0; k4 < ENC/4; k4++) {
        float4 ww = w4[k4];
        #pragma unroll
        for (int b = 0; b < NB; b++) {
            float4 xx = ((float4*)xs)[b*(ENC/4) + k4];
            f[b] += ww.x*xx.x + ww.y*xx.y + ww.z*xx.z + ww.w*xx.w;
        }
    }
    float mu = 0.f;
    #pragma unroll
    for (int b = 0; b < NB; b++) mu += f[b];
    mu *= (1.0f/NB);
    float var = 0.f;
    #pragma unroll
    for (int b = 0; b < NB; b++) { float d = f[b]-mu; var += d*d; }
    var *= (1.0f/NB);
    float s = rsqrtf(var + 1e-5f) * gam[j];
    float bb = bet[j];
    #pragma unroll
    for (int b = 0; b < NB; b++)
        g_seq[b*(LSEQ*EMB) + j] = (f[b]-mu)*s + bb;   // t = 0
}

// ---------------- kernel 2: embedding gather -> seq[:,1:,:] ----------------
__global__ void embed_kernel(const int* __restrict__ y,      // [16,255]
                             const float* __restrict__ emb)  // [32000,256]
{
    int blk = blockIdx.x;            // 16*255 blocks
    int b = blk / (LSEQ-1), t = blk % (LSEQ-1);
    int row = y[b*(LSEQ-1) + t];
    const float4* src = (const float4*)(emb + (long)row*EMB);
    float4* dst = (float4*)(g_seq + b*(LSEQ*EMB) + (t+1)*EMB);
    dst[threadIdx.x] = src[threadIdx.x];   // 64 threads * float4 = 256 floats
}

// ---------------- tf32 helpers ----------------
__device__ __forceinline__ unsigned f2tf32(float v)
{
    unsigned u;
    asm("cvt.rna.tf32.f32 %0, %1;" : "=r"(u) : "f"(v));
    return u;
}

__device__ __forceinline__ void mma_tf32(float* c, const unsigned* a, const unsigned* b)
{
    asm volatile(
        "mma.sync.aligned.m16n8k8.row.col.f32.tf32.tf32.f32 "
        "{%0,%1,%2,%3}, {%4,%5,%6,%7}, {%8,%9}, {%0,%1,%2,%3};\n"
        : "+f"(c[0]), "+f"(c[1]), "+f"(c[2]), "+f"(c[3])
        : "r"(a[0]), "r"(a[1]), "r"(a[2]), "r"(a[3]), "r"(b[0]), "r"(b[1]));
}

#define TF_KS    32
#define TF_AST   36                        // smem row stride in floats (conflict-free)
#define TF_TILE  (128*TF_AST)              // floats per matrix tile
#define TF_SMEM  (2*2*TF_TILE*4)           // 73728 B

// ---------------- kernel 3: generic tf32 GEMM  C = A[M,K] * B[N,K]^T (+bias) ----------------
// MODE 0: C[m*Cld+n] (+tanh opt);  MODE 1: C[t*(N*16) + n*16 + b], m = b*256+t
template<int MODE, bool DOTANH>
__global__ void __launch_bounds__(256, 2) gemm_tf32(
    const float* __restrict__ A, const float* __restrict__ B,
    const float* __restrict__ bias0, const float* __restrict__ bias1,
    float* __restrict__ C, int N, int K, int Cld)
{
    extern __shared__ float smf[];
    const int tid  = threadIdx.x;
    const int lane = tid & 31;
    const int warp = tid >> 5;
    const int warp_m = warp >> 1;
    const int warp_n = warp & 1;
    const int m0 = blockIdx.y * 128;
    const int n0 = blockIdx.x * 128;
    const int g = lane >> 2;
    const int t = lane & 3;

    unsigned sbase = (unsigned)__cvta_generic_to_shared(smf);

    auto issue_load = [&](int buf, int k0) {
        #pragma unroll
        for (int rep = 0; rep < 8; rep++) {
            int i   = tid + rep*256;
            int mat = i >> 10;
            int idx = i & 1023;
            int row = idx >> 3;
            int q   = idx & 7;
            unsigned daddr = sbase + ((buf*2 + mat)*TF_TILE + row*TF_AST + q*4)*4;
            const float* gsrc = (mat ? B + (long)(n0+row)*K
                                     : A + (long)(m0+row)*K) + k0 + q*4;
            asm volatile("cp.async.cg.shared.global [%0], [%1], 16;\n"
                         :: "r"(daddr), "l"(gsrc));
        }
        asm volatile("cp.async.commit_group;\n");
    };

    float acc[2][8][4];
    #pragma unroll
    for (int i = 0; i < 2; i++)
        #pragma unroll
        for (int j = 0; j < 8; j++)
            #pragma unroll
            for (int r = 0; r < 4; r++) acc[i][j][r] = 0.f;

    issue_load(0, 0);

    int nst = K / TF_KS;
    int buf = 0;
    for (int ks = 0; ks < nst; ks++) {
        asm volatile("cp.async.wait_group 0;\n");
        __syncthreads();
        if (ks + 1 < nst) issue_load(buf ^ 1, (ks+1)*TF_KS);

        const float* sA = smf + (buf*2 + 0)*TF_TILE;
        const float* sB = smf + (buf*2 + 1)*TF_TILE;

        #pragma unroll
        for (int k8 = 0; k8 < 4; k8++) {
            int kc = k8*8 + t;
            unsigned af[2][4];
            #pragma unroll
            for (int im = 0; im < 2; im++) {
                int rb = warp_m*32 + im*16 + g;
                af[im][0] = f2tf32(sA[rb*TF_AST + kc]);
                af[im][1] = f2tf32(sA[(rb+8)*TF_AST + kc]);
                af[im][2] = f2tf32(sA[rb*TF_AST + kc + 4]);
                af[im][3] = f2tf32(sA[(rb+8)*TF_AST + kc + 4]);
            }
            unsigned bf[8][2];
            #pragma unroll
            for (int in = 0; in < 8; in++) {
                int nc = warp_n*64 + in*8 + g;
                bf[in][0] = f2tf32(sB[nc*TF_AST + kc]);
                bf[in][1] = f2tf32(sB[nc*TF_AST + kc + 4]);
            }
            #pragma unroll
            for (int im = 0; im < 2; im++)
                #pragma unroll
                for (int in = 0; in < 8; in++)
                    mma_tf32(acc[im][in], af[im], bf[in]);
        }
        buf ^= 1;
        __syncthreads();
    }

    #pragma unroll
    for (int im = 0; im < 2; im++) {
        int row = m0 + warp_m*32 + im*16 + g;
        #pragma unroll
        for (int in = 0; in < 8; in++) {
            int col = n0 + warp_n*64 + in*8 + t*2;
            float bs0 = 0.f, bs1 = 0.f;
            if (bias0) { bs0 += bias0[col]; bs1 += bias0[col+1]; }
            if (bias1) { bs0 += bias1[col]; bs1 += bias1[col+1]; }
            float v00 = acc[im][in][0] + bs0, v01 = acc[im][in][1] + bs1;
            float v10 = acc[im][in][2] + bs0, v11 = acc[im][in][3] + bs1;
            if (DOTANH) { v00 = tanhf(v00); v01 = tanhf(v01);
                          v10 = tanhf(v10); v11 = tanhf(v11); }
            if (MODE == 0) {
                *(float2*)(C + (long)row*Cld + col)     = make_float2(v00, v01);
                *(float2*)(C + (long)(row+8)*Cld + col) = make_float2(v10, v11);
            } else {
                int b0 = row >> 8, t0 = row & 255;
                int b1 = (row+8) >> 8, t1 = (row+8) & 255;
                C[(long)t0*(N*NB) + col*NB + b0]     = v00;
                C[(long)t0*(N*NB) + (col+1)*NB + b0] = v01;
                C[(long)t1*(N*NB) + col*NB + b1]     = v10;
                C[(long)t1*(N*NB) + (col+1)*NB + b1] = v11;
            }
        }
    }
}

// ---------------- kernel 4: persistent LSTM (128 CTAs, tensor-core recurrence) ----------------
// Warp w owns k-slice [w*64, w*64+64). W (hi/lo tf32) fragments live in registers
// across all 256 steps. Per step: 48 m16n8k8 MMAs/warp (3-pass exact), 8-way smem
// reduction, fp32 gates. h ring transposed; out buffered in smem.
#define LSTM_CTAS 128
#define HROW 516                       // h smem row stride (floats): (4g+t)%32 conflict-free
#define SM_HS   0                      // 16*516 = 8256 floats
#define SM_GX   8256                   // 256 floats
#define SM_RED  8512                   // 8*272 = 2176 floats (b-stride 17)
#define SM_OUTB 10688                  // 16384 floats
#define LSTM_SMEM ((10688 + 16384)*4)  // 108288 B

__global__ void __launch_bounds__(256, 1) lstm_kernel(
    const float* __restrict__ xw,
    const float* __restrict__ Whh,   // [2048,512]
    float* __restrict__ out, long bstr, long tstr)
{
    extern __shared__ float smf[];
    float* hsw  = smf + SM_HS;
    float* gx   = smf + SM_GX;
    float* red  = smf + SM_RED;
    float* outb = smf + SM_OUTB;

    int tid = threadIdx.x, cta = blockIdx.x;
    int gate = tid >> 6, dl = (tid >> 4) & 3, b = tid & 15;
    int j  = gate*512 + cta*4 + dl;

    const int w    = tid >> 5;       // warp = k-slice owner
    const int lane = tid & 31;
    const int g    = lane >> 2;      // 0..7
    const int tq   = lane & 3;       // 0..3

    // --- preload W fragments (hi/lo tf32) for this warp's k-slice, once ---
    unsigned wh[2][8][2], wl[2][8][2];
    #pragma unroll
    for (int nb = 0; nb < 2; nb++) {
        int jl = nb*8 + g;
        const float* wrow = Whh + (long)((jl>>2)*512 + cta*4 + (jl&3))*512 + w*64;
        #pragma unroll
        for (int k8 = 0; k8 < 8; k8++) {
            float w0 = wrow[k8*8 + tq];
            float w1 = wrow[k8*8 + tq + 4];
            unsigned h0 = f2tf32(w0), h1 = f2tf32(w1);
            wh[nb][k8][0] = h0;
            wh[nb][k8][1] = h1;
            wl[nb][k8][0] = f2tf32(w0 - __uint_as_float(h0));
            wl[nb][k8][1] = f2tf32(w1 - __uint_as_float(h1));
        }
    }

    // zero h slot 0
    for (int i = cta*256 + tid; i < NB*DEC; i += LSTM_CTAS*256)
        g_hT[i] = 0.f;

    const int q   = tid >> 6;        // batch quad
    const int dl0 = tid & 63;
    const int jl_me = gate*4 + dl;   // this thread's j-local (0..15)
    float c_reg = 0.f;
    grid_barrier128(cta);

    for (int t = 0; t < LSEQ; t++) {
        // prefetch xw (independent of h)
        float xwv = xw[(long)t*(G4*NB) + j*NB + b];

        // stage h(t): global [q][d][br] -> smem hsw[b][d]
        const float4* hsrc4 = (const float4*)(g_hT + (t & 1)*(NB*DEC));
        #pragma unroll
        for (int r = 0; r < 8; r++) {
            int d = r*64 + dl0;
            float4 v = __ldcg(hsrc4 + q*512 + d);
            hsw[(4*q+0)*HROW + d] = v.x;
            hsw[(4*q+1)*HROW + d] = v.y;
            hsw[(4*q+2)*HROW + d] = v.z;
            hsw[(4*q+3)*HROW + d] = v.w;
        }
        __syncthreads();

        // tensor-core partial D[16b x 16jl] over this warp's k-slice (3-pass exact)
        float acc[2][2][4];
        #pragma unroll
        for (int nb = 0; nb < 2; nb++)
            #pragma unroll
            for (int p = 0; p < 2; p++)
                #pragma unroll
                for (int r = 0; r < 4; r++) acc[nb][p][r] = 0.f;

        #pragma unroll
        for (int k8 = 0; k8 < 8; k8++) {
            int kb = w*64 + k8*8;
            float v0 = hsw[g*HROW + kb + tq];
            float v1 = hsw[(g+8)*HROW + kb + tq];
            float v2 = hsw[g*HROW + kb + tq + 4];
            float v3 = hsw[(g+8)*HROW + kb + tq + 4];
            unsigned ah[4], al[4];
            ah[0] = f2tf32(v0); ah[1] = f2tf32(v1);
            ah[2] = f2tf32(v2); ah[3] = f2tf32(v3);
            al[0] = f2tf32(v0 - __uint_as_float(ah[0]));
            al[1] = f2tf32(v1 - __uint_as_float(ah[1]));
            al[2] = f2tf32(v2 - __uint_as_float(ah[2]));
            al[3] = f2tf32(v3 - __uint_as_float(ah[3]));
            int p = k8 & 1;
            #pragma unroll
            for (int nb = 0; nb < 2; nb++) {
                mma_tf32(acc[nb][p], ah, wh[nb][k8]);
                mma_tf32(acc[nb][p], ah, wl[nb][k8]);
                mma_tf32(acc[nb][p], al, wh[nb][k8]);
            }
        }

        // write warp partials: rows g/g+8 (=b), cols nb*8+2tq(+1) (=jl), stride 17
        #pragma unroll
        for (int nb = 0; nb < 2; nb++) {
            int cbase = nb*8 + 2*tq;
            red[w*272 + g*17 + cbase]         = acc[nb][0][0] + acc[nb][1][0];
            red[w*272 + g*17 + cbase + 1]     = acc[nb][0][1] + acc[nb][1][1];
            red[w*272 + (g+8)*17 + cbase]     = acc[nb][0][2] + acc[nb][1][2];
            red[w*272 + (g+8)*17 + cbase + 1] = acc[nb][0][3] + acc[nb][1][3];
        }
        __syncthreads();

        // reduce 8 warps' partials + xw
        float s = xwv;
        #pragma unroll
        for (int ww = 0; ww < 8; ww++)
            s += red[ww*272 + b*17 + jl_me];
        gx[tid] = s;
        __syncthreads();

        if (tid < 64) {
            float ig = sigf(gx[tid]);
            float fg = sigf(gx[64 + tid]);
            float gg = tanhf(gx[128 + tid]);
            float og = sigf(gx[192 + tid]);
            c_reg = fg*c_reg + ig*gg;
            float h = og * tanhf(c_reg);
            int ddl = tid >> 4, bb = tid & 15;
            __stcg(&g_hT[(((t+1) & 1))*(NB*DEC)
                         + (bb >> 2)*2048 + cta*16 + ddl*4 + (bb & 3)], h);
            outb[t*64 + bb*4 + ddl] = h;
        }
        grid_barrier128(cta);
    }

    // final dump of out buffer
    for (int i = tid; i < 4096; i += 256) {
        int tt = i >> 4, bb = i & 15;
        float4 v = ((const float4*)outb)[i];
        *(float4*)(out + bb*bstr + (long)tt*tstr + cta*4) = v;
    }
}

// ---------------- kernel 5: causal self-attention (CTA per (q,b)) ----------------
__global__ void __launch_bounds__(256) attn_kernel()
{
    __shared__ float hqs[512];
    __shared__ float sc[256];
    __shared__ float red[256];
    int q = blockIdx.x, b = blockIdx.y;
    int tid = threadIdx.x;
    int nk = q + 1;
    float* catb = g_cat + (long)b*(LSEQ*2*DEC);

    if (tid < 128)
        ((float4*)hqs)[tid] = ((const float4*)(catb + q*1024 + 512))[tid];
    __syncthreads();

    int w = tid >> 5, lane = tid & 31;
    for (int k = w; k < nk; k += 8) {
        const float4* hk = (const float4*)(catb + k*1024 + 512);
        float s = 0.f;
        #pragma unroll
        for (int i = 0; i < 4; i++) {
            float4 a = ((float4*)hqs)[lane + 32*i];
            float4 c = hk[lane + 32*i];
            s += a.x*c.x + a.y*c.y + a.z*c.z + a.w*c.w;
        }
        #pragma unroll
        for (int off = 16; off; off >>= 1) s += __shfl_xor_sync(0xffffffffu, s, off);
        if (lane == 0) sc[k] = s;
    }
    __syncthreads();

    float v = (tid < nk) ? sc[tid] : -INFINITY;
    red[tid] = v; __syncthreads();
    #pragma unroll
    for (int s = 128; s; s >>= 1) {
        if (tid < s) red[tid] = fmaxf(red[tid], red[tid+s]);
        __syncthreads();
    }
    float mx = red[0]; __syncthreads();
    float e = (tid < nk) ? __expf(v - mx) : 0.f;
    red[tid] = e; __syncthreads();
    #pragma unroll
    for (int s = 128; s; s >>= 1) {
        if (tid < s) red[tid] += red[tid+s];
        __syncthreads();
    }
    float inv = 1.f / red[0];
    __syncthreads();
    if (tid < nk) sc[tid] = e * inv;
    __syncthreads();

    float a0 = 0.f, a1 = 0.f;
    for (int k = 0; k < nk; k++) {
        float wk = sc[k];
        const float* hk = catb + k*1024 + 512;
        a0 += wk * hk[tid];
        a1 += wk * hk[tid + 256];
    }
    catb[q*1024 + tid]       = a0;
    catb[q*1024 + tid + 256] = a1;
}

// ---------------- kernel 6: fc2 single-pass tf32 tensor GEMM (proven) ----------------
__global__ void __launch_bounds__(256, 2) fc2_tf32_kernel(
    const float* __restrict__ A, const float* __restrict__ B,
    const float* __restrict__ bias, float* __restrict__ C)
{
    extern __shared__ float smf[];
    const int tid  = threadIdx.x;
    const int lane = tid & 31;
    const int warp = tid >> 5;
    const int warp_m = warp >> 1;
    const int warp_n = warp & 1;
    const int m0 = blockIdx.y * 128;
    const int n0 = blockIdx.x * 128;
    const int g = lane >> 2;
    const int t = lane & 3;

    unsigned sbase = (unsigned)__cvta_generic_to_shared(smf);

    auto issue_load = [&](int buf, int k0) {
        #pragma unroll
        for (int rep = 0; rep < 8; rep++) {
            int i   = tid + rep*256;
            int mat = i >> 10;
            int idx = i & 1023;
            int row = idx >> 3;
            int q   = idx & 7;
            unsigned daddr = sbase + ((buf*2 + mat)*TF_TILE + row*TF_AST + q*4)*4;
            const float* gsrc = (mat ? B + (long)(n0+row)*DEC
                                     : A + (long)(m0+row)*DEC) + k0 + q*4;
            asm volatile("cp.async.cg.shared.global [%0], [%1], 16;\n"
                         :: "r"(daddr), "l"(gsrc));
        }
        asm volatile("cp.async.commit_group;\n");
    };

    float acc[2][8][4];
    #pragma unroll
    for (int i = 0; i < 2; i++)
        #pragma unroll
        for (int j = 0; j < 8; j++)
            #pragma unroll
            for (int r = 0; r < 4; r++) acc[i][j][r] = 0.f;

    issue_load(0, 0);

    int buf = 0;
    for (int ks = 0; ks < DEC/TF_KS; ks++) {
        asm volatile("cp.async.wait_group 0;\n");
        __syncthreads();
        if (ks + 1 < DEC/TF_KS) issue_load(buf ^ 1, (ks+1)*TF_KS);

        const float* sA = smf + (buf*2 + 0)*TF_TILE;
        const float* sB = smf + (buf*2 + 1)*TF_TILE;

        #pragma unroll
        for (int k8 = 0; k8 < 4; k8++) {
            int kc = k8*8 + t;
            unsigned af[2][4];
            #pragma unroll
            for (int im = 0; im < 2; im++) {
                int rb = warp_m*32 + im*16 + g;
                af[im][0] = f2tf32(sA[rb*TF_AST + kc]);
                af[im][1] = f2tf32(sA[(rb+8)*TF_AST + kc]);
                af[im][2] = f2tf32(sA[rb*TF_AST + kc + 4]);
                af[im][3] = f2tf32(sA[(rb+8)*TF_AST + kc + 4]);
            }
            unsigned bf[8][2];
            #pragma unroll
            for (int in = 0; in < 8; in++) {
                int nc = warp_n*64 + in*8 + g;
                bf[in][0] = f2tf32(sB[nc*TF_AST + kc]);
                bf[in][1] = f2tf32(sB[nc*TF_AST + kc + 4]);
            }
            #pragma unroll
            for (int im = 0; im < 2; im++)
                #pragma unroll
                for (int in = 0; in < 8; in++)
                    mma_tf32(acc[im][in], af[im], bf[in]);
        }
        buf ^= 1;
        __syncthreads();
    }

    #pragma unroll
    for (int im = 0; im < 2; im++) {
        int row = m0 + warp_m*32 + im*16 + g;
        #pragma unroll
        for (int in = 0; in < 8; in++) {
            int col = n0 + warp_n*64 + in*8 + t*2;
            float b0 = bias[col], b1 = bias[col+1];
            float2 v0 = make_float2(acc[im][in][0] + b0, acc[im][in][1] + b1);
            float2 v1 = make_float2(acc[im][in][2] + b0, acc[im][in][3] + b1);
            *(float2*)(C + (long)row*NV + col)     = v0;
            *(float2*)(C + (long)(row+8)*NV + col) = v1;
        }
    }
}

// ---------------- launch ----------------
extern "C" void kernel_launch(void* const* d_in, const int* in_sizes, int n_in,
                              void* d_out, int out_size)
{
    const float* x       = (const float*)d_in[0];
    const int*   y       = (const int*)  d_in[1];
    const float* fc1_w   = (const float*)d_in[2];
    const float* fc1_b   = (const float*)d_in[3];
    const float* bn_g    = (const float*)d_in[4];
    const float* bn_b    = (const float*)d_in[5];
    const float* emb     = (const float*)d_in[6];
    const float* l1_Wih  = (const float*)d_in[7];
    const float* l1_Whh  = (const float*)d_in[8];
    const float* l1_bih  = (const float*)d_in[9];
    const float* l1_bhh  = (const float*)d_in[10];
    const float* attn_W  = (const float*)d_in[11];
    const float* dc_Wih  = (const float*)d_in[12];
    const float* dc_Whh  = (const float*)d_in[13];
    const float* dc_bih  = (const float*)d_in[14];
    const float* dc_bhh  = (const float*)d_in[15];
    const float* fc2_w   = (const float*)d_in[16];
    const float* fc2_b   = (const float*)d_in[17];
    float* out = (float*)d_out;

    float *p_seq, *p_xw, *p_cat, *p_attn, *p_h2;
    cudaGetSymbolAddress((void**)&p_seq,  g_seq);
    cudaGetSymbolAddress((void**)&p_xw,   g_xw);
    cudaGetSymbolAddress((void**)&p_cat,  g_cat);
    cudaGetSymbolAddress((void**)&p_attn, g_attn);
    cudaGetSymbolAddress((void**)&p_h2,   g_h2);

    cudaFuncSetAttribute(lstm_kernel, cudaFuncAttributeMaxDynamicSharedMemorySize, LSTM_SMEM);
    cudaFuncSetAttribute(fc2_tf32_kernel, cudaFuncAttributeMaxDynamicSharedMemorySize, TF_SMEM);
    cudaFuncSetAttribute(gemm_tf32<1,false>, cudaFuncAttributeMaxDynamicSharedMemorySize, TF_SMEM);
    cudaFuncSetAttribute(gemm_tf32<0,true>,  cudaFuncAttributeMaxDynamicSharedMemorySize, TF_SMEM);

    // 1. fc1 + BN
    fc1_bn_kernel<<<1, 256>>>(x, fc1_w, fc1_b, bn_g, bn_b);
    // 2. embedding
    embed_kernel<<<NB*(LSEQ-1), 64>>>(y, emb);
    // 3. xw1 = seq @ l1_Wih^T + biases   (tf32, LSTM layout)
    gemm_tf32<1,false><<<dim3(G4/128, MROWS/128), 256, TF_SMEM>>>(
        p_seq, l1_Wih, l1_bih, l1_bhh, p_xw, G4, EMB, 0);
    // 4. LSTM 1  ->  g_cat[b][t][512:1024]
    lstm_kernel<<<LSTM_CTAS, 256, LSTM_SMEM>>>(
        p_xw, l1_Whh, p_cat + 512, (long)LSEQ*2*DEC, (long)2*DEC);
    // 5. attention -> g_cat[b][t][0:512]
    attn_kernel<<<dim3(LSEQ, NB), 256>>>();
    // 6. attn = tanh(cat @ attn_W^T)   (tf32)
    gemm_tf32<0,true><<<dim3(DEC/128, MROWS/128), 256, TF_SMEM>>>(
        p_cat, attn_W, nullptr, nullptr, p_attn, DEC, 2*DEC, DEC);
    // 7. xw2 = attn @ dc_Wih^T + biases (tf32, LSTM layout)
    gemm_tf32<1,false><<<dim3(G4/128, MROWS/128), 256, TF_SMEM>>>(
        p_attn, dc_Wih, dc_bih, dc_bhh, p_xw, G4, DEC, 0);
    // 8. LSTM 2 -> g_h2[m][d]
    lstm_kernel<<<LSTM_CTAS, 256, LSTM_SMEM>>>(
        p_xw, dc_Whh, p_h2, (long)LSEQ*DEC, (long)DEC);
    // 9. fc2 single-pass tf32 tensor GEMM -> d_out
    fc2_tf32_kernel<<<dim3(NV/128, MROWS/128), 256, TF_SMEM>>>(
        p_h2, fc2_w, fc2_b, out);
}

// round 13
// speedup vs baseline: 1.8045x; 1.0331x over previous
#include <cuda_runtime.h>
#include <cuda_bf16.h>
#include <math.h>

// ---------------- problem constants ----------------
#define NB   16          // batch
#define LSEQ 256         // sequence length (TY+1)
#define ENC  512
#define EMB  256
#define DEC  512
#define NV   32000
#define G4   2048        // 4*DEC
#define MROWS 4096       // NB*LSEQ

// ---------------- scratch (__device__ globals; no allocs) ----------------
__device__ float g_seq [NB*LSEQ*EMB];        //  4 MB  [b][t][EMB]
__device__ float g_xw  [LSEQ*G4*NB];         // 32 MB  [t][j][b]
__device__ float g_cat [NB*LSEQ*2*DEC];      // 16 MB  [b][t][ mix(512) | h1(512) ]
__device__ float g_attn[MROWS*DEC];          //  8 MB  [m][512]
__device__ float g_h2  [MROWS*DEC];          //  8 MB  [m][512]
// h double buffer, TRANSPOSED layout: word = q*2048 + d*4 + br  (b = 4q+br)
__device__ float g_hT  [2*NB*DEC];
// hierarchical barrier state (zero-initialized; every barrier self-resets)
__device__ unsigned          g_leaf[16*32];  // 16 counters, 128B apart
__device__ unsigned          g_root;
__device__ volatile unsigned g_gen;

__device__ __forceinline__ float sigf(float x){ return 1.0f/(1.0f+__expf(-x)); }

// ---------------- hierarchical grid barrier (128 CTAs: 16 leaves x 8) ----------------
__device__ __forceinline__ void grid_barrier128(int cta)
{
    __syncthreads();
    if (threadIdx.x == 0) {
        __threadfence();
        unsigned gen = g_gen;
        unsigned leaf = (unsigned)cta & 15u;
        if (atomicAdd(&g_leaf[leaf*32], 1u) == 7u) {
            g_leaf[leaf*32] = 0u;
            __threadfence();
            if (atomicAdd(&g_root, 1u) == 15u) {
                g_root = 0u;
                __threadfence();
                g_gen = gen + 1u;
            } else {
                while (g_gen == gen) { }
            }
        } else {
            while (g_gen == gen) { }
        }
    }
    __syncthreads();
}

// ---------------- kernel 1: fc1 + BatchNorm (batch stats) -> seq[:,0,:] ----------------
__global__ void __launch_bounds__(256) fc1_bn_kernel(
    const float* __restrict__ x,     // [16,512]
    const float* __restrict__ w,     // [256,512]
    const float* __restrict__ bias,  // [256]
    const float* __restrict__ gam,   // [256]
    const float* __restrict__ bet)   // [256]
{
    __shared__ float xs[NB*ENC];     // 32 KB
    int tid = threadIdx.x;
    for (int i = tid; i < NB*ENC/4; i += 256)
        ((float4*)xs)[i] = ((const float4*)x)[i];
    __syncthreads();

    int j = tid;                     // one feature per thread (EMB == 256)
    float f[NB];
    #pragma unroll
    for (int b = 0; b < NB; b++) f[b] = bias[j];

    const float4* w4 = (const float4*)(w + j*ENC);
    for (int k4 = 0; k4 < ENC/4; k4++) {
        float4 ww = w4[k4];
        #pragma unroll
        for (int b = 0; b < NB; b++) {
            float4 xx = ((float4*)xs)[b*(ENC/4) + k4];
            f[b] += ww.x*xx.x + ww.y*xx.y + ww.z*xx.z + ww.w*xx.w;
        }
    }
    float mu = 0.f;
    #pragma unroll
    for (int b = 0; b < NB; b++) mu += f[b];
    mu *= (1.0f/NB);
    float var = 0.f;
    #pragma unroll
    for (int b = 0; b < NB; b++) { float d = f[b]-mu; var += d*d; }
    var *= (1.0f/NB);
    float s = rsqrtf(var + 1e-5f) * gam[j];
    float bb = bet[j];
    #pragma unroll
    for (int b = 0; b < NB; b++)
        g_seq[b*(LSEQ*EMB) + j] = (f[b]-mu)*s + bb;   // t = 0
}

// ---------------- kernel 2: embedding gather -> seq[:,1:,:] ----------------
__global__ void embed_kernel(const int* __restrict__ y,      // [16,255]
                             const float* __restrict__ emb)  // [32000,256]
{
    int blk = blockIdx.x;            // 16*255 blocks
    int b = blk / (LSEQ-1), t = blk % (LSEQ-1);
    int row = y[b*(LSEQ-1) + t];
    const float4* src = (const float4*)(emb + (long)row*EMB);
    float4* dst = (float4*)(g_seq + b*(LSEQ*EMB) + (t+1)*EMB);
    dst[threadIdx.x] = src[threadIdx.x];   // 64 threads * float4 = 256 floats
}

// ---------------- tf32 helpers ----------------
__device__ __forceinline__ unsigned f2tf32(float v)
{
    unsigned u;
    asm("cvt.rna.tf32.f32 %0, %1;" : "=r"(u) : "f"(v));
    return u;
}

__device__ __forceinline__ void mma_tf32(float* c, const unsigned* a, const unsigned* b)
{
    asm volatile(
        "mma.sync.aligned.m16n8k8.row.col.f32.tf32.tf32.f32 "
        "{%0,%1,%2,%3}, {%4,%5,%6,%7}, {%8,%9}, {%0,%1,%2,%3};\n"
        : "+f"(c[0]), "+f"(c[1]), "+f"(c[2]), "+f"(c[3])
        : "r"(a[0]), "r"(a[1]), "r"(a[2]), "r"(a[3]), "r"(b[0]), "r"(b[1]));
}

__device__ __forceinline__ void mma_bf16(float* c, const unsigned* a, const unsigned* b)
{
    asm volatile(
        "mma.sync.aligned.m16n8k16.row.col.f32.bf16.bf16.f32 "
        "{%0,%1,%2,%3}, {%4,%5,%6,%7}, {%8,%9}, {%0,%1,%2,%3};\n"
        : "+f"(c[0]), "+f"(c[1]), "+f"(c[2]), "+f"(c[3])
        : "r"(a[0]), "r"(a[1]), "r"(a[2]), "r"(a[3]), "r"(b[0]), "r"(b[1]));
}

#define TF_KS    32
#define TF_AST   36                        // smem row stride in floats (conflict-free)
#define TF_TILE  (128*TF_AST)              // floats per matrix tile
#define TF_SMEM  (2*2*TF_TILE*4)           // 73728 B

// ---------------- kernel 3: generic tf32 GEMM  C = A[M,K] * B[N,K]^T (+bias) ----------------
// MODE 0: C[m*Cld+n] (+tanh opt);  MODE 1: C[t*(N*16) + n*16 + b], m = b*256+t
template<int MODE, bool DOTANH>
__global__ void __launch_bounds__(256, 2) gemm_tf32(
    const float* __restrict__ A, const float* __restrict__ B,
    const float* __restrict__ bias0, const float* __restrict__ bias1,
    float* __restrict__ C, int N, int K, int Cld)
{
    extern __shared__ float smf[];
    const int tid  = threadIdx.x;
    const int lane = tid & 31;
    const int warp = tid >> 5;
    const int warp_m = warp >> 1;
    const int warp_n = warp & 1;
    const int m0 = blockIdx.y * 128;
    const int n0 = blockIdx.x * 128;
    const int g = lane >> 2;
    const int t = lane & 3;

    unsigned sbase = (unsigned)__cvta_generic_to_shared(smf);

    auto issue_load = [&](int buf, int k0) {
        #pragma unroll
        for (int rep = 0; rep < 8; rep++) {
            int i   = tid + rep*256;
            int mat = i >> 10;
            int idx = i & 1023;
            int row = idx >> 3;
            int q   = idx & 7;
            unsigned daddr = sbase + ((buf*2 + mat)*TF_TILE + row*TF_AST + q*4)*4;
            const float* gsrc = (mat ? B + (long)(n0+row)*K
                                     : A + (long)(m0+row)*K) + k0 + q*4;
            asm volatile("cp.async.cg.shared.global [%0], [%1], 16;\n"
                         :: "r"(daddr), "l"(gsrc));
        }
        asm volatile("cp.async.commit_group;\n");
    };

    float acc[2][8][4];
    #pragma unroll
    for (int i = 0; i < 2; i++)
        #pragma unroll
        for (int j = 0; j < 8; j++)
            #pragma unroll
            for (int r = 0; r < 4; r++) acc[i][j][r] = 0.f;

    issue_load(0, 0);

    int nst = K / TF_KS;
    int buf = 0;
    for (int ks = 0; ks < nst; ks++) {
        asm volatile("cp.async.wait_group 0;\n");
        __syncthreads();
        if (ks + 1 < nst) issue_load(buf ^ 1, (ks+1)*TF_KS);

        const float* sA = smf + (buf*2 + 0)*TF_TILE;
        const float* sB = smf + (buf*2 + 1)*TF_TILE;

        #pragma unroll
        for (int k8 = 0; k8 < 4; k8++) {
            int kc = k8*8 + t;
            unsigned af[2][4];
            #pragma unroll
            for (int im = 0; im < 2; im++) {
                int rb = warp_m*32 + im*16 + g;
                af[im][0] = f2tf32(sA[rb*TF_AST + kc]);
                af[im][1] = f2tf32(sA[(rb+8)*TF_AST + kc]);
                af[im][2] = f2tf32(sA[rb*TF_AST + kc + 4]);
                af[im][3] = f2tf32(sA[(rb+8)*TF_AST + kc + 4]);
            }
            unsigned bf[8][2];
            #pragma unroll
            for (int in = 0; in < 8; in++) {
                int nc = warp_n*64 + in*8 + g;
                bf[in][0] = f2tf32(sB[nc*TF_AST + kc]);
                bf[in][1] = f2tf32(sB[nc*TF_AST + kc + 4]);
            }
            #pragma unroll
            for (int im = 0; im < 2; im++)
                #pragma unroll
                for (int in = 0; in < 8; in++)
                    mma_tf32(acc[im][in], af[im], bf[in]);
        }
        buf ^= 1;
        __syncthreads();
    }

    #pragma unroll
    for (int im = 0; im < 2; im++) {
        int row = m0 + warp_m*32 + im*16 + g;
        #pragma unroll
        for (int in = 0; in < 8; in++) {
            int col = n0 + warp_n*64 + in*8 + t*2;
            float bs0 = 0.f, bs1 = 0.f;
            if (bias0) { bs0 += bias0[col]; bs1 += bias0[col+1]; }
            if (bias1) { bs0 += bias1[col]; bs1 += bias1[col+1]; }
            float v00 = acc[im][in][0] + bs0, v01 = acc[im][in][1] + bs1;
            float v10 = acc[im][in][2] + bs0, v11 = acc[im][in][3] + bs1;
            if (DOTANH) { v00 = tanhf(v00); v01 = tanhf(v01);
                          v10 = tanhf(v10); v11 = tanhf(v11); }
            if (MODE == 0) {
                *(float2*)(C + (long)row*Cld + col)     = make_float2(v00, v01);
                *(float2*)(C + (long)(row+8)*Cld + col) = make_float2(v10, v11);
            } else {
                int b0 = row >> 8, t0 = row & 255;
                int b1 = (row+8) >> 8, t1 = (row+8) & 255;
                C[(long)t0*(N*NB) + col*NB + b0]     = v00;
                C[(long)t0*(N*NB) + (col+1)*NB + b0] = v01;
                C[(long)t1*(N*NB) + col*NB + b1]     = v10;
                C[(long)t1*(N*NB) + (col+1)*NB + b1] = v11;
            }
        }
    }
}

// ---------------- kernel 4: persistent LSTM (128 CTAs, bf16 hi/lo tensor cores) ----------------
// Warp w owns k-slice [w*64, w*64+64). W (hi/lo bf16, packed pairs) lives in registers.
// h is split once per step into packed-bf16 hi/lo smem planes during staging.
// Per step per warp: 24 m16n8k16 MMAs (3-pass hi/lo), 8-way smem reduction, fp32 gates.
#define LSTM_CTAS 128
#define HP2  260                       // plane row stride (u32): bank = 4g+tq, bijective
#define SM_HI   0                      // 16*260 u32
#define SM_LO   4160                   // 16*260 u32
#define SM_GX   8320                   // 256 floats
#define SM_RED  8576                   // 8*272 floats
#define LSTM_SMEM ((8576 + 2176)*4)    // 43008 B

__global__ void __launch_bounds__(256, 1) lstm_kernel(
    const float* __restrict__ xw,
    const float* __restrict__ Whh,   // [2048,512]
    float* __restrict__ out, long bstr, long tstr)
{
    extern __shared__ unsigned smu[];
    unsigned* hiP = smu + SM_HI;
    unsigned* loP = smu + SM_LO;
    float*    gx  = (float*)(smu + SM_GX);
    float*    red = (float*)(smu + SM_RED);

    int tid = threadIdx.x, cta = blockIdx.x;
    int gate = tid >> 6, dl = (tid >> 4) & 3, b = tid & 15;
    int j  = gate*512 + cta*4 + dl;

    const int w    = tid >> 5;       // warp = k-slice owner
    const int lane = tid & 31;
    const int g    = lane >> 2;      // 0..7
    const int tq   = lane & 3;       // 0..3

    // --- preload W fragments (hi/lo bf16 packed pairs) for this warp's k-slice ---
    unsigned wh[2][4][2], wl[2][4][2];
    #pragma unroll
    for (int nb = 0; nb < 2; nb++) {
        int jl = nb*8 + g;
        const float* wrow = Whh + (long)((jl>>2)*512 + cta*4 + (jl&3))*512 + w*64;
        #pragma unroll
        for (int c = 0; c < 4; c++) {
            float2 p0 = *(const float2*)(wrow + c*16 + 2*tq);
            float2 p1 = *(const float2*)(wrow + c*16 + 2*tq + 8);
            __nv_bfloat162 h0 = __floats2bfloat162_rn(p0.x, p0.y);
            __nv_bfloat162 h1 = __floats2bfloat162_rn(p1.x, p1.y);
            wh[nb][c][0] = *(unsigned*)&h0;
            wh[nb][c][1] = *(unsigned*)&h1;
            __nv_bfloat162 l0 = __floats2bfloat162_rn(
                p0.x - __bfloat162float(h0.x), p0.y - __bfloat162float(h0.y));
            __nv_bfloat162 l1 = __floats2bfloat162_rn(
                p1.x - __bfloat162float(h1.x), p1.y - __bfloat162float(h1.y));
            wl[nb][c][0] = *(unsigned*)&l0;
            wl[nb][c][1] = *(unsigned*)&l1;
        }
    }

    // zero h slot 0
    for (int i = cta*256 + tid; i < NB*DEC; i += LSTM_CTAS*256)
        g_hT[i] = 0.f;

    const int q   = tid >> 6;        // batch quad
    const int dl0 = tid & 63;
    const int jl_me = gate*4 + dl;   // this thread's j-local (0..15)
    float c_reg = 0.f;
    float h_out = 0.f;
    grid_barrier128(cta);

    for (int t = 0; t < LSEQ; t++) {
        // prefetch xw (independent of h)
        float xwv = xw[(long)t*(G4*NB) + j*NB + b];

        // stage + split h(t): global [q][d][br] -> packed bf16 hi/lo planes [b][d/2]
        const float4* hsrc4 = (const float4*)(g_hT + (t & 1)*(NB*DEC));
        #pragma unroll
        for (int r = 0; r < 4; r++) {
            int d0 = r*128 + dl0*2;
            float4 va = __ldcg(hsrc4 + q*512 + d0);
            float4 vb = __ldcg(hsrc4 + q*512 + d0 + 1);
            int dp = d0 >> 1;
            #pragma unroll
            for (int i = 0; i < 4; i++) {
                float x0 = (i==0)?va.x:(i==1)?va.y:(i==2)?va.z:va.w;
                float x1 = (i==0)?vb.x:(i==1)?vb.y:(i==2)?vb.z:vb.w;
                __nv_bfloat162 hv = __floats2bfloat162_rn(x0, x1);
                __nv_bfloat162 lv = __floats2bfloat162_rn(
                    x0 - __bfloat162float(hv.x), x1 - __bfloat162float(hv.y));
                hiP[(4*q+i)*HP2 + dp] = *(unsigned*)&hv;
                loP[(4*q+i)*HP2 + dp] = *(unsigned*)&lv;
            }
        }
        __syncthreads();

        // bf16 tensor-core partial D[16b x 16jl] over this warp's k-slice (3-pass)
        float acc[2][2][4];
        #pragma unroll
        for (int nb = 0; nb < 2; nb++)
            #pragma unroll
            for (int p = 0; p < 2; p++)
                #pragma unroll
                for (int r = 0; r < 4; r++) acc[nb][p][r] = 0.f;

        #pragma unroll
        for (int c = 0; c < 4; c++) {
            int kb2 = (w*64 + c*16) >> 1;    // u32 index
            unsigned ah[4], al[4];
            ah[0] = hiP[g*HP2 + kb2 + tq];
            ah[1] = hiP[(g+8)*HP2 + kb2 + tq];
            ah[2] = hiP[g*HP2 + kb2 + tq + 4];
            ah[3] = hiP[(g+8)*HP2 + kb2 + tq + 4];
            al[0] = loP[g*HP2 + kb2 + tq];
            al[1] = loP[(g+8)*HP2 + kb2 + tq];
            al[2] = loP[g*HP2 + kb2 + tq + 4];
            al[3] = loP[(g+8)*HP2 + kb2 + tq + 4];
            int p = c & 1;
            #pragma unroll
            for (int nb = 0; nb < 2; nb++) {
                mma_bf16(acc[nb][p], ah, wh[nb][c]);
                mma_bf16(acc[nb][p], ah, wl[nb][c]);
                mma_bf16(acc[nb][p], al, wh[nb][c]);
            }
        }

        // write warp partials: rows g/g+8 (=b), cols nb*8+2tq(+1) (=jl), stride 17
        #pragma unroll
        for (int nb = 0; nb < 2; nb++) {
            int cbase = nb*8 + 2*tq;
            red[w*272 + g*17 + cbase]         = acc[nb][0][0] + acc[nb][1][0];
            red[w*272 + g*17 + cbase + 1]     = acc[nb][0][1] + acc[nb][1][1];
            red[w*272 + (g+8)*17 + cbase]     = acc[nb][0][2] + acc[nb][1][2];
            red[w*272 + (g+8)*17 + cbase + 1] = acc[nb][0][3] + acc[nb][1][3];
        }
        __syncthreads();

        // reduce 8 warps' partials + xw; all 256 threads do their own transcendental
        float s = xwv;
        #pragma unroll
        for (int ww = 0; ww < 8; ww++)
            s += red[ww*272 + b*17 + jl_me];
        gx[tid] = (gate == 2) ? tanhf(s) : sigf(s);
        __syncthreads();

        if (tid < 64) {
            float ig = gx[tid];
            float fg = gx[64 + tid];
            float gg = gx[128 + tid];
            float og = gx[192 + tid];
            c_reg = fg*c_reg + ig*gg;
            h_out = og * tanhf(c_reg);
            int ddl = tid >> 4, bb = tid & 15;
            __stcg(&g_hT[(((t+1) & 1))*(NB*DEC)
                         + (bb >> 2)*2048 + cta*16 + ddl*4 + (bb & 3)], h_out);
        }
        grid_barrier128(cta);
        // out store after the barrier arrival: not in the fence's drain set
        if (tid < 64) {
            int ddl = tid >> 4, bb = tid & 15;
            out[bb*bstr + (long)t*tstr + cta*4 + ddl] = h_out;
        }
    }
}

// ---------------- kernel 5: causal self-attention (CTA per (q,b)) ----------------
__global__ void __launch_bounds__(256) attn_kernel()
{
    __shared__ float hqs[512];
    __shared__ float sc[256];
    __shared__ float red[256];
    __shared__ float4 red4[256];
    int q = blockIdx.x, b = blockIdx.y;
    int tid = threadIdx.x;
    int nk = q + 1;
    float* catb = g_cat + (long)b*(LSEQ*2*DEC);

    if (tid < 128)
        ((float4*)hqs)[tid] = ((const float4*)(catb + q*1024 + 512))[tid];
    __syncthreads();

    int w = tid >> 5, lane = tid & 31;
    for (int k = w; k < nk; k += 8) {
        const float4* hk = (const float4*)(catb + k*1024 + 512);
        float s = 0.f;
        #pragma unroll
        for (int i = 0; i < 4; i++) {
            float4 a = ((float4*)hqs)[lane + 32*i];
            float4 c = hk[lane + 32*i];
            s += a.x*c.x + a.y*c.y + a.z*c.z + a.w*c.w;
        }
        #pragma unroll
        for (int off = 16; off; off >>= 1) s += __shfl_xor_sync(0xffffffffu, s, off);
        if (lane == 0) sc[k] = s;
    }
    __syncthreads();

    float v = (tid < nk) ? sc[tid] : -INFINITY;
    red[tid] = v; __syncthreads();
    #pragma unroll
    for (int s = 128; s; s >>= 1) {
        if (tid < s) red[tid] = fmaxf(red[tid], red[tid+s]);
        __syncthreads();
    }
    float mx = red[0]; __syncthreads();
    float e = (tid < nk) ? __expf(v - mx) : 0.f;
    red[tid] = e; __syncthreads();
    #pragma unroll
    for (int s = 128; s; s >>= 1) {
        if (tid < s) red[tid] += red[tid+s];
        __syncthreads();
    }
    float inv = 1.f / red[0];
    __syncthreads();
    if (tid < nk) sc[tid] = e * inv;
    __syncthreads();

    // mix: float4 per thread, 2 k-stripes
    int dq = tid & 127;
    int stripe = tid >> 7;
    float4 a = make_float4(0.f, 0.f, 0.f, 0.f);
    for (int k = stripe; k < nk; k += 2) {
        float wk = sc[k];
        float4 hv = *(const float4*)(catb + k*1024 + 512 + dq*4);
        a.x += wk*hv.x; a.y += wk*hv.y; a.z += wk*hv.z; a.w += wk*hv.w;
    }
    red4[tid] = a;
    __syncthreads();
    if (tid < 128) {
        float4 b0 = red4[tid], b1 = red4[tid+128];
        float4 r = make_float4(b0.x+b1.x, b0.y+b1.y, b0.z+b1.z, b0.w+b1.w);
        *(float4*)(catb + q*1024 + dq*4) = r;
    }
}

// ---------------- kernel 6: fc2 single-pass tf32 tensor GEMM (proven) ----------------
__global__ void __launch_bounds__(256, 2) fc2_tf32_kernel(
    const float* __restrict__ A, const float* __restrict__ B,
    const float* __restrict__ bias, float* __restrict__ C)
{
    extern __shared__ float smf[];
    const int tid  = threadIdx.x;
    const int lane = tid & 31;
    const int warp = tid >> 5;
    const int warp_m = warp >> 1;
    const int warp_n = warp & 1;
    const int m0 = blockIdx.y * 128;
    const int n0 = blockIdx.x * 128;
    const int g = lane >> 2;
    const int t = lane & 3;

    unsigned sbase = (unsigned)__cvta_generic_to_shared(smf);

    auto issue_load = [&](int buf, int k0) {
        #pragma unroll
        for (int rep = 0; rep < 8; rep++) {
            int i   = tid + rep*256;
            int mat = i >> 10;
            int idx = i & 1023;
            int row = idx >> 3;
            int q   = idx & 7;
            unsigned daddr = sbase + ((buf*2 + mat)*TF_TILE + row*TF_AST + q*4)*4;
            const float* gsrc = (mat ? B + (long)(n0+row)*DEC
                                     : A + (long)(m0+row)*DEC) + k0 + q*4;
            asm volatile("cp.async.cg.shared.global [%0], [%1], 16;\n"
                         :: "r"(daddr), "l"(gsrc));
        }
        asm volatile("cp.async.commit_group;\n");
    };

    float acc[2][8][4];
    #pragma unroll
    for (int i = 0; i < 2; i++)
        #pragma unroll
        for (int j = 0; j < 8; j++)
            #pragma unroll
            for (int r = 0; r < 4; r++) acc[i][j][r] = 0.f;

    issue_load(0, 0);

    int buf = 0;
    for (int ks = 0; ks < DEC/TF_KS; ks++) {
        asm volatile("cp.async.wait_group 0;\n");
        __syncthreads();
        if (ks + 1 < DEC/TF_KS) issue_load(buf ^ 1, (ks+1)*TF_KS);

        const float* sA = smf + (buf*2 + 0)*TF_TILE;
        const float* sB = smf + (buf*2 + 1)*TF_TILE;

        #pragma unroll
        for (int k8 = 0; k8 < 4; k8++) {
            int kc = k8*8 + t;
            unsigned af[2][4];
            #pragma unroll
            for (int im = 0; im < 2; im++) {
                int rb = warp_m*32 + im*16 + g;
                af[im][0] = f2tf32(sA[rb*TF_AST + kc]);
                af[im][1] = f2tf32(sA[(rb+8)*TF_AST + kc]);
                af[im][2] = f2tf32(sA[rb*TF_AST + kc + 4]);
                af[im][3] = f2tf32(sA[(rb+8)*TF_AST + kc + 4]);
            }
            unsigned bf[8][2];
            #pragma unroll
            for (int in = 0; in < 8; in++) {
                int nc = warp_n*64 + in*8 + g;
                bf[in][0] = f2tf32(sB[nc*TF_AST + kc]);
                bf[in][1] = f2tf32(sB[nc*TF_AST + kc + 4]);
            }
            #pragma unroll
            for (int im = 0; im < 2; im++)
                #pragma unroll
                for (int in = 0; in < 8; in++)
                    mma_tf32(acc[im][in], af[im], bf[in]);
        }
        buf ^= 1;
        __syncthreads();
    }

    #pragma unroll
    for (int im = 0; im < 2; im++) {
        int row = m0 + warp_m*32 + im*16 + g;
        #pragma unroll
        for (int in = 0; in < 8; in++) {
            int col = n0 + warp_n*64 + in*8 + t*2;
            float b0 = bias[col], b1 = bias[col+1];
            float2 v0 = make_float2(acc[im][in][0] + b0, acc[im][in][1] + b1);
            float2 v1 = make_float2(acc[im][in][2] + b0, acc[im][in][3] + b1);
            *(float2*)(C + (long)row*NV + col)     = v0;
            *(float2*)(C + (long)(row+8)*NV + col) = v1;
        }
    }
}

// ---------------- launch ----------------
extern "C" void kernel_launch(void* const* d_in, const int* in_sizes, int n_in,
                              void* d_out, int out_size)
{
    const float* x       = (const float*)d_in[0];
    const int*   y       = (const int*)  d_in[1];
    const float* fc1_w   = (const float*)d_in[2];
    const float* fc1_b   = (const float*)d_in[3];
    const float* bn_g    = (const float*)d_in[4];
    const float* bn_b    = (const float*)d_in[5];
    const float* emb     = (const float*)d_in[6];
    const float* l1_Wih  = (const float*)d_in[7];
    const float* l1_Whh  = (const float*)d_in[8];
    const float* l1_bih  = (const float*)d_in[9];
    const float* l1_bhh  = (const float*)d_in[10];
    const float* attn_W  = (const float*)d_in[11];
    const float* dc_Wih  = (const float*)d_in[12];
    const float* dc_Whh  = (const float*)d_in[13];
    const float* dc_bih  = (const float*)d_in[14];
    const float* dc_bhh  = (const float*)d_in[15];
    const float* fc2_w   = (const float*)d_in[16];
    const float* fc2_b   = (const float*)d_in[17];
    float* out = (float*)d_out;

    float *p_seq, *p_xw, *p_cat, *p_attn, *p_h2;
    cudaGetSymbolAddress((void**)&p_seq,  g_seq);
    cudaGetSymbolAddress((void**)&p_xw,   g_xw);
    cudaGetSymbolAddress((void**)&p_cat,  g_cat);
    cudaGetSymbolAddress((void**)&p_attn, g_attn);
    cudaGetSymbolAddress((void**)&p_h2,   g_h2);

    cudaFuncSetAttribute(lstm_kernel, cudaFuncAttributeMaxDynamicSharedMemorySize, LSTM_SMEM);
    cudaFuncSetAttribute(fc2_tf32_kernel, cudaFuncAttributeMaxDynamicSharedMemorySize, TF_SMEM);
    cudaFuncSetAttribute(gemm_tf32<1,false>, cudaFuncAttributeMaxDynamicSharedMemorySize, TF_SMEM);
    cudaFuncSetAttribute(gemm_tf32<0,true>,  cudaFuncAttributeMaxDynamicSharedMemorySize, TF_SMEM);

    // 1. fc1 + BN
    fc1_bn_kernel<<<1, 256>>>(x, fc1_w, fc1_b, bn_g, bn_b);
    // 2. embedding
    embed_kernel<<<NB*(LSEQ-1), 64>>>(y, emb);
    // 3. xw1 = seq @ l1_Wih^T + biases   (tf32, LSTM layout)
    gemm_tf32<1,false><<<dim3(G4/128, MROWS/128), 256, TF_SMEM>>>(
        p_seq, l1_Wih, l1_bih, l1_bhh, p_xw, G4, EMB, 0);
    // 4. LSTM 1  ->  g_cat[b][t][512:1024]
    lstm_kernel<<<LSTM_CTAS, 256, LSTM_SMEM>>>(
        p_xw, l1_Whh, p_cat + 512, (long)LSEQ*2*DEC, (long)2*DEC);
    // 5. attention -> g_cat[b][t][0:512]
    attn_kernel<<<dim3(LSEQ, NB), 256>>>();
    // 6. attn = tanh(cat @ attn_W^T)   (tf32)
    gemm_tf32<0,true><<<dim3(DEC/128, MROWS/128), 256, TF_SMEM>>>(
        p_cat, attn_W, nullptr, nullptr, p_attn, DEC, 2*DEC, DEC);
    // 7. xw2 = attn @ dc_Wih^T + biases (tf32, LSTM layout)
    gemm_tf32<1,false><<<dim3(G4/128, MROWS/128), 256, TF_SMEM>>>(
        p_attn, dc_Wih, dc_bih, dc_bhh, p_xw, G4, DEC, 0);
    // 8. LSTM 2 -> g_h2[m][d]
    lstm_kernel<<<LSTM_CTAS, 256, LSTM_SMEM>>>(
        p_xw, dc_Whh, p_h2, (long)LSEQ*DEC, (long)DEC);
    // 9. fc2 single-pass tf32 tensor GEMM -> d_out
    fc2_tf32_kernel<<<dim3(NV/128, MROWS/128), 256, TF_SMEM>>>(
        p_h2, fc2_w, fc2_b, out);
}